// round 8
// baseline (speedup 1.0000x reference)
#include <cuda_runtime.h>
#include <math.h>
#include <stdint.h>

#define BB 4
#define CC 64
#define C3 192
#define TT 10
#define HH 64
#define WW 64
#define HW 4096
#define THW 40960
#define HEADS 4
#define CPH 16
#define NN 160
#define DD 4096
#define BH (BB*HEADS)
#define KSPL 8
#define KCH (DD/KSPL)   // 512

// ---------------- scratch (device globals) ---------------------------------
__device__ float g_qkv0[(size_t)BB * C3 * THW];
__device__ float g_qkv1[(size_t)BB * C3 * THW];
__device__ float g_Spart[(size_t)KSPL * BH * NN * NN];
__device__ float g_S[(size_t)BH * NN * NN];
__device__ float g_norm2[BB * 128 * TT];           // sum of squares, q:ch<64, k:ch 64..127
__device__ float g_O[(size_t)BB * CC * THW];

// ---------------- packed f32x2 helpers --------------------------------------
__device__ __forceinline__ void ffma2(unsigned long long& d,
                                      unsigned long long a, unsigned long long b) {
    asm("fma.rn.f32x2 %0, %1, %2, %0;" : "+l"(d) : "l"(a), "l"(b));
}
__device__ __forceinline__ unsigned long long dup2(float x) {
    unsigned long long r;
    asm("mov.b64 %0, {%1, %1};" : "=l"(r) : "f"(x));
    return r;
}
__device__ __forceinline__ float2 unpk(unsigned long long v) {
    float2 r;
    asm("mov.b64 {%0, %1}, %2;" : "=f"(r.x), "=f"(r.y) : "l"(v));
    return r;
}
__device__ __forceinline__ unsigned long long lds64(const float* p) {
    return *(const unsigned long long*)p;
}
__device__ __forceinline__ uint32_t smem_u32(const void* p) {
    uint32_t a;
    asm("{ .reg .u64 t; cvta.to.shared.u64 t, %1; cvt.u32.u64 %0, t; }" : "=r"(a) : "l"(p));
    return a;
}
__device__ __forceinline__ void cpasync16(uint32_t dst, const void* src) {
    asm volatile("cp.async.cg.shared.global [%0], [%1], 16;" :: "r"(dst), "l"(src));
}
#define CP_COMMIT() asm volatile("cp.async.commit_group;" ::: "memory")
#define CP_WAIT1()  asm volatile("cp.async.wait_group 1;" ::: "memory")
#define CP_WAIT0()  asm volatile("cp.async.wait_group 0;" ::: "memory")

// ---------------- K1 / K7: projection GEMM (FFMA2, multi-CTA/SM) ------------
__global__ __launch_bounds__(128) void gemm_proj2(
    const float* __restrict__ W, const float* __restrict__ X, float* __restrict__ Y,
    long xbstride, long ybstride)
{
    __shared__ __align__(16) float As2[32][132];
    __shared__ __align__(16) float Bs[32][132];
    const int b  = blockIdx.z;
    const int m0 = blockIdx.y * 64;
    const int p0 = blockIdx.x * 128;
    const float* Xb = X + (size_t)b * xbstride;
    float*       Yb = Y + (size_t)b * ybstride;
    const int tid = threadIdx.x;
    const int tm = tid >> 4, tn = tid & 15;

    // one block zeroes the norm accumulator for this pass
    if (blockIdx.x == 0 && blockIdx.y == 0 && blockIdx.z == 0) {
        for (int i = tid; i < BB * 128 * TT; i += 128) g_norm2[i] = 0.f;
    }

    unsigned long long acc[8][4];
    #pragma unroll
    for (int i = 0; i < 8; i++)
        #pragma unroll
        for (int j = 0; j < 4; j++) acc[i][j] = 0ull;

    for (int kb = 0; kb < 64; kb += 32) {
        #pragma unroll
        for (int j = 0; j < 4; j++) {
            int idx = tid + j * 128;
            int row = idx >> 3;
            int kc  = (idx & 7) * 4;
            float4 w4 = *(const float4*)&W[(size_t)(m0 + row) * 64 + kb + kc];
            *(unsigned long long*)&As2[kc + 0][2 * row] = dup2(w4.x);
            *(unsigned long long*)&As2[kc + 1][2 * row] = dup2(w4.y);
            *(unsigned long long*)&As2[kc + 2][2 * row] = dup2(w4.z);
            *(unsigned long long*)&As2[kc + 3][2 * row] = dup2(w4.w);
        }
        #pragma unroll
        for (int j = 0; j < 8; j++) {
            int idx = tid + j * 128;
            int row = idx >> 5;
            int col = (idx & 31) * 4;
            *(float4*)&Bs[row][col] = *(const float4*)&Xb[(size_t)(kb + row) * THW + p0 + col];
        }
        __syncthreads();
        #pragma unroll 4
        for (int k = 0; k < 32; k++) {
            unsigned long long a[8], bp[4];
            // A pairs are 16B-aligned (base 64*tm bytes): 4x LDS.128
            const ulonglong2* ap = (const ulonglong2*)&As2[k][16 * tm];
            #pragma unroll
            for (int q = 0; q < 4; q++) {
                ulonglong2 w2 = ap[q];
                a[2 * q]     = w2.x;
                a[2 * q + 1] = w2.y;
            }
            #pragma unroll
            for (int u = 0; u < 4; u++)    bp[u] = lds64(&Bs[k][2 * tn + 32 * u]);
            #pragma unroll
            for (int mi = 0; mi < 8; mi++)
                #pragma unroll
                for (int u = 0; u < 4; u++) ffma2(acc[mi][u], a[mi], bp[u]);
        }
        __syncthreads();
    }
    #pragma unroll
    for (int mi = 0; mi < 8; mi++) {
        size_t base = (size_t)(m0 + tm * 8 + mi) * THW + p0 + 2 * tn;
        #pragma unroll
        for (int u = 0; u < 4; u++)
            *(float2*)&Yb[base + 32 * u] = unpk(acc[mi][u]);
    }
}

// ---------------- K2: depthwise 3x3 + temporal mix + fused norm^2 -----------
__global__ __launch_bounds__(256) void dwconv_tmix(
    const float* __restrict__ wdw, const float* __restrict__ wt,
    const float* __restrict__ bt)
{
    __shared__ float tile[TT][18][18];
    const int bc = blockIdx.z;
    const int c  = bc % C3;
    const int h0 = blockIdx.y * 16, w0 = blockIdx.x * 16;
    const float* src = g_qkv0 + (size_t)bc * THW;
    float*       dst = g_qkv1 + (size_t)bc * THW;
    const int tid = threadIdx.x;

    for (int idx = tid; idx < TT * 18 * 18; idx += 256) {
        int t = idx / 324, rem = idx % 324;
        int y = rem / 18, x = rem % 18;
        int gh = h0 + y - 1, gw = w0 + x - 1;
        float v = 0.f;
        if (gh >= 0 && gh < HH && gw >= 0 && gw < WW)
            v = src[(size_t)t * HW + gh * WW + gw];
        tile[t][y][x] = v;
    }
    __syncthreads();

    float wd[9];
    #pragma unroll
    for (int i = 0; i < 9; i++) wd[i] = wdw[c * 9 + i];

    const int y = tid >> 4, x = tid & 15;
    float cv[TT];
    #pragma unroll
    for (int t = 0; t < TT; t++) {
        float s = 0.f;
        #pragma unroll
        for (int kh = 0; kh < 3; kh++)
            #pragma unroll
            for (int kw = 0; kw < 3; kw++)
                s += wd[kh * 3 + kw] * tile[t][y + kh][x + kw];
        cv[t] = s;
    }
    const int hw = (h0 + y) * WW + (w0 + x);
    float outv[TT];
    #pragma unroll
    for (int s = 0; s < TT; s++) {
        float o = bt[s];
        #pragma unroll
        for (int t = 0; t < TT; t++) o += wt[s * TT + t] * cv[t];
        outv[s] = o;
        dst[(size_t)s * HW + hw] = o;
    }
    // fused L2-norm^2 accumulation for q/k channels
    if (c < 128) {
        const int b = bc / C3;
        float* np = g_norm2 + (size_t)(b * 128 + c) * TT;
        #pragma unroll
        for (int s = 0; s < TT; s++) {
            float sq = outv[s] * outv[s];
            #pragma unroll
            for (int off = 16; off; off >>= 1)
                sq += __shfl_xor_sync(0xffffffffu, sq, off);
            if ((tid & 31) == 0) atomicAdd(&np[s], sq);
        }
    }
}

// ---------------- K3b: S partials = Q K^T -----------------------------------
// 512 threads (4 warps/SMSP), 160x160 tile, micro 5x(5x2) FFMA2, dup-A smem,
// register-prefetch double buffering, split-K = 8.
#define QAS 330                        // dup-A row stride (floats)
#define QBS 166                        // K row stride (floats)
#define QK_STG (32 * QAS + 32 * QBS)   // one stage, floats

__global__ __launch_bounds__(512, 1) void qk_gemm6()
{
    extern __shared__ __align__(16) float sm[];
    const int bh = blockIdx.x;
    const int ks = blockIdx.y;
    const int b = bh >> 2, h = bh & 3;
    const float* Q  = g_qkv1 + ((size_t)b * C3 + h * CPH) * THW + (size_t)ks * KCH;
    const float* Kp = Q + (size_t)CC * THW;
    const int tid = threadIdx.x;
    const int tm = tid >> 4;            // 0..31 -> rows tm*5..tm*5+4
    const int tn = tid & 15;            // 0..15 -> col pairs 10tn..10tn+9

    int lisK[5], lrow[5], lseg[5];
    #pragma unroll
    for (int j = 0; j < 5; j++) {
        int idx = tid + j * 512;
        lisK[j] = idx >= 1280;
        int l = idx - lisK[j] * 1280;
        lrow[j] = l >> 3;
        lseg[j] = (l & 7) * 4;
    }

    unsigned long long acc[5][5];
    #pragma unroll
    for (int i = 0; i < 5; i++)
        #pragma unroll
        for (int j = 0; j < 5; j++) acc[i][j] = 0ull;

    float4 r[5];
    auto gload = [&](int c) {
        const int kb = c * 32;
        #pragma unroll
        for (int j = 0; j < 5; j++)
            r[j] = *(const float4*)((lisK[j] ? Kp : Q) + (size_t)lrow[j] * DD + kb + lseg[j]);
    };
    auto sstore = [&](int s) {
        float* Qs2 = sm + s * QK_STG;
        float* Ksh = Qs2 + 32 * QAS;
        #pragma unroll
        for (int j = 0; j < 5; j++) {
            if (lisK[j]) {
                Ksh[(lseg[j] + 0) * QBS + lrow[j]] = r[j].x;
                Ksh[(lseg[j] + 1) * QBS + lrow[j]] = r[j].y;
                Ksh[(lseg[j] + 2) * QBS + lrow[j]] = r[j].z;
                Ksh[(lseg[j] + 3) * QBS + lrow[j]] = r[j].w;
            } else {
                *(unsigned long long*)&Qs2[(lseg[j] + 0) * QAS + 2 * lrow[j]] = dup2(r[j].x);
                *(unsigned long long*)&Qs2[(lseg[j] + 1) * QAS + 2 * lrow[j]] = dup2(r[j].y);
                *(unsigned long long*)&Qs2[(lseg[j] + 2) * QAS + 2 * lrow[j]] = dup2(r[j].z);
                *(unsigned long long*)&Qs2[(lseg[j] + 3) * QAS + 2 * lrow[j]] = dup2(r[j].w);
            }
        }
    };

    gload(0);
    sstore(0);
    __syncthreads();

    for (int c = 0; c < 16; c++) {
        if (c < 15) gload(c + 1);
        const float* Qs2 = sm + (c & 1) * QK_STG;
        const float* Ksh = Qs2 + 32 * QAS;
        #pragma unroll 8
        for (int k = 0; k < 32; k++) {
            unsigned long long a[5], bp[5];
            #pragma unroll
            for (int g = 0; g < 5; g++) a[g]  = lds64(&Qs2[k * QAS + 10 * tm + 2 * g]);
            #pragma unroll
            for (int u = 0; u < 5; u++) bp[u] = lds64(&Ksh[k * QBS + 10 * tn + 2 * u]);
            #pragma unroll
            for (int g = 0; g < 5; g++)
                #pragma unroll
                for (int u = 0; u < 5; u++) ffma2(acc[g][u], a[g], bp[u]);
        }
        if (c < 15) sstore((c + 1) & 1);
        __syncthreads();
    }

    float* Sp = g_Spart + ((size_t)ks * BH + bh) * NN * NN;
    #pragma unroll
    for (int g = 0; g < 5; g++) {
        int gi = tm * 5 + g;
        #pragma unroll
        for (int u = 0; u < 5; u++)
            *(float2*)&Sp[(size_t)gi * NN + 10 * tn + 2 * u] = unpk(acc[g][u]);
    }
}

// ---------------- K3c: reduce split-K + norms + scale + softmax -------------
__global__ __launch_bounds__(256) void softmax2(const float* __restrict__ temp)
{
    const int warp = (blockIdx.x * 256 + threadIdx.x) >> 5;
    const int lane = threadIdx.x & 31;
    if (warp >= BH * NN) return;
    const int bh = warp / NN, i = warp % NN;
    const int h = bh & 3, b = bh >> 2;
    const float* nq = g_norm2 + (size_t)(b * 128 + h * CPH) * TT;        // + i
    const float* nk = g_norm2 + (size_t)(b * 128 + 64 + h * CPH) * TT;   // + j
    const float invq = 1.f / fmaxf(sqrtf(nq[i]), 1e-12f);
    const float scale_i = invq * temp[h];
    float vals[5];
    float mx = -1e30f;
    #pragma unroll
    for (int j5 = 0; j5 < 5; j5++) {
        int j = lane + j5 * 32;
        float s = 0.f;
        #pragma unroll
        for (int ks = 0; ks < KSPL; ks++)
            s += g_Spart[(((size_t)ks * BH + bh) * NN + i) * NN + j];
        float invk = 1.f / fmaxf(sqrtf(nk[j]), 1e-12f);
        vals[j5] = s * scale_i * invk;
        mx = fmaxf(mx, vals[j5]);
    }
    #pragma unroll
    for (int off = 16; off; off >>= 1) mx = fmaxf(mx, __shfl_xor_sync(0xffffffffu, mx, off));
    float s = 0.f;
    #pragma unroll
    for (int j5 = 0; j5 < 5; j5++) { vals[j5] = __expf(vals[j5] - mx); s += vals[j5]; }
    #pragma unroll
    for (int off = 16; off; off >>= 1) s += __shfl_xor_sync(0xffffffffu, s, off);
    const float invs = 1.f / s;
    float* row = g_S + (size_t)bh * NN * NN + (size_t)i * NN;
    #pragma unroll
    for (int j5 = 0; j5 < 5; j5++) row[lane + j5 * 32] = vals[j5] * invs;
}

// ---------------- K3d: O = P V ----------------------------------------------
// 256 threads, 2 CTAs/SM, tile 80(i) x 256(d), micro 5x(8x2), cp.async 2-stage.
#define PS 36                          // P row stride (floats)
#define VS 264                         // V row stride (floats)
#define PV_STAGE (80 * PS + 32 * VS)   // floats

__global__ __launch_bounds__(256, 2) void pv_gemm5()
{
    extern __shared__ __align__(16) float sm[];
    const uint32_t sbase = smem_u32(sm);
    const int bh = blockIdx.z;
    const int b = bh >> 2, h = bh & 3;
    const int i0 = blockIdx.y * 80;
    const int d0 = blockIdx.x * 256;
    const float* P = g_S + (size_t)bh * NN * NN;
    const float* V = g_qkv1 + ((size_t)b * C3 + 2 * CC + h * CPH) * THW;
    float*       O = g_O   + ((size_t)b * CC + h * CPH) * THW;
    const int tid = threadIdx.x;
    const int tm = tid >> 4, tn = tid & 15;

    auto copy_chunk = [&](int c, int s) {
        const int kb = c * 32;
        #pragma unroll
        for (int j = 0; j < 3; j++) {
            int idx = tid + j * 256;
            if (idx < 640) {
                int row = idx >> 3, seg = idx & 7;
                cpasync16(sbase + (uint32_t)(s * PV_STAGE + row * PS + seg * 4) * 4u,
                          P + (size_t)(i0 + row) * NN + kb + seg * 4);
            }
        }
        #pragma unroll
        for (int j = 0; j < 8; j++) {
            int idx = tid + j * 256;
            int row = idx >> 6, col = (idx & 63) * 4;
            cpasync16(sbase + (uint32_t)(s * PV_STAGE + 80 * PS + row * VS + col) * 4u,
                      V + (size_t)(kb + row) * DD + d0 + col);
        }
        CP_COMMIT();
    };

    unsigned long long acc[5][8];
    #pragma unroll
    for (int i = 0; i < 5; i++)
        #pragma unroll
        for (int j = 0; j < 8; j++) acc[i][j] = 0ull;

    copy_chunk(0, 0);
    copy_chunk(1, 1);

    for (int c = 0; c < 5; c++) {
        if (c < 4) { CP_WAIT1(); } else { CP_WAIT0(); }
        __syncthreads();
        const float* Ps = sm + (c & 1) * PV_STAGE;
        const float* Vs = Ps + 80 * PS;
        #pragma unroll 4
        for (int k = 0; k < 32; k++) {
            unsigned long long bp[8];
            #pragma unroll
            for (int u = 0; u < 8; u++)
                bp[u] = lds64(&Vs[k * VS + 2 * tn + 32 * u]);
            #pragma unroll
            for (int v = 0; v < 5; v++) {
                unsigned long long a = dup2(Ps[(tm * 5 + v) * PS + k]);
                #pragma unroll
                for (int u = 0; u < 8; u++) ffma2(acc[v][u], a, bp[u]);
            }
        }
        __syncthreads();
        if (c < 3) copy_chunk(c + 2, c & 1);
    }

    #pragma unroll
    for (int v = 0; v < 5; v++) {
        size_t base = (size_t)(i0 + tm * 5 + v) * DD + d0 + 2 * tn;
        #pragma unroll
        for (int u = 0; u < 8; u++)
            *(float2*)&O[base + 32 * u] = unpk(acc[v][u]);
    }
}

// ---------------- host launcher --------------------------------------------
extern "C" void kernel_launch(void* const* d_in, const int* in_sizes, int n_in,
                              void* d_out, int out_size)
{
    const float* x      = (const float*)d_in[0];
    const float* w_qkv  = (const float*)d_in[1];
    const float* w_dw   = (const float*)d_in[2];
    const float* w_t    = (const float*)d_in[3];
    const float* b_t    = (const float*)d_in[4];
    const float* temp   = (const float*)d_in[5];
    const float* w_out  = (const float*)d_in[6];
    float* out = (float*)d_out;

    float *qkv0, *obuf;
    cudaGetSymbolAddress((void**)&qkv0, g_qkv0);
    cudaGetSymbolAddress((void**)&obuf, g_O);

    const int qk_smem = 2 * QK_STG * 4;     // 126976 B
    const int pv_smem = 2 * PV_STAGE * 4;   // 90624 B
    cudaFuncSetAttribute(qk_gemm6, cudaFuncAttributeMaxDynamicSharedMemorySize, qk_smem);
    cudaFuncSetAttribute(pv_gemm5, cudaFuncAttributeMaxDynamicSharedMemorySize, pv_smem);

    // K1: qkv projection (also zeroes g_norm2)
    gemm_proj2<<<dim3(THW / 128, C3 / 64, BB), 128>>>(
        w_qkv, x, qkv0, (long)CC * THW, (long)C3 * THW);

    // K2: depthwise 3x3 + temporal mix + fused norm^2
    dwconv_tmix<<<dim3(4, 4, BB * C3), 256>>>(w_dw, w_t, b_t);

    // K3b: split-K scores (512 threads, 4 warps/SMSP)
    qk_gemm6<<<dim3(BH, KSPL), 512, qk_smem>>>();

    // K3c: reduce + norms + scale + softmax
    softmax2<<<(BH * NN) / 8, 256>>>(temp);

    // K3d: O = P V (2 CTAs/SM, cp.async)
    pv_gemm5<<<dim3(DD / 256, NN / 80, BH), 256, pv_smem>>>();

    // K7: final projection -> d_out
    gemm_proj2<<<dim3(THW / 128, 1, BB), 128>>>(
        w_out, obuf, out, (long)CC * THW, (long)CC * THW);
}

// round 9
// speedup vs baseline: 1.0537x; 1.0537x over previous
#include <cuda_runtime.h>
#include <math.h>
#include <stdint.h>

#define BB 4
#define CC 64
#define C3 192
#define TT 10
#define HH 64
#define WW 64
#define HW 4096
#define THW 40960
#define HEADS 4
#define CPH 16
#define NN 160
#define DD 4096
#define BH (BB*HEADS)
#define KSPL 8
#define KCH (DD/KSPL)   // 512

// ---------------- scratch (device globals) ---------------------------------
__device__ float g_qkv0[(size_t)BB * C3 * THW];
__device__ float g_qkv1[(size_t)BB * C3 * THW];
__device__ float g_Spart[(size_t)KSPL * BH * NN * NN];
__device__ float g_S[(size_t)BH * NN * NN];
__device__ float g_norm2[BB * 128 * TT];   // sum sq; q: ch<64, k: ch 64..127
__device__ float g_O[(size_t)BB * CC * THW];

// ---------------- packed f32x2 helpers --------------------------------------
__device__ __forceinline__ void ffma2(unsigned long long& d,
                                      unsigned long long a, unsigned long long b) {
    asm("fma.rn.f32x2 %0, %1, %2, %0;" : "+l"(d) : "l"(a), "l"(b));
}
__device__ __forceinline__ unsigned long long dup2(float x) {
    unsigned long long r;
    asm("mov.b64 %0, {%1, %1};" : "=l"(r) : "f"(x));
    return r;
}
__device__ __forceinline__ float2 unpk(unsigned long long v) {
    float2 r;
    asm("mov.b64 {%0, %1}, %2;" : "=f"(r.x), "=f"(r.y) : "l"(v));
    return r;
}
__device__ __forceinline__ unsigned long long lds64(const float* p) {
    return *(const unsigned long long*)p;
}
__device__ __forceinline__ uint32_t smem_u32(const void* p) {
    uint32_t a;
    asm("{ .reg .u64 t; cvta.to.shared.u64 t, %1; cvt.u32.u64 %0, t; }" : "=r"(a) : "l"(p));
    return a;
}
__device__ __forceinline__ void cpasync16(uint32_t dst, const void* src) {
    asm volatile("cp.async.cg.shared.global [%0], [%1], 16;" :: "r"(dst), "l"(src));
}
#define CP_COMMIT() asm volatile("cp.async.commit_group;" ::: "memory")
#define CP_WAIT1()  asm volatile("cp.async.wait_group 1;" ::: "memory")
#define CP_WAIT0()  asm volatile("cp.async.wait_group 0;" ::: "memory")

// ---------------- K1 / K7: projection GEMM (FFMA2, multi-CTA/SM) ------------
__global__ __launch_bounds__(128) void gemm_proj2(
    const float* __restrict__ W, const float* __restrict__ X, float* __restrict__ Y,
    long xbstride, long ybstride)
{
    __shared__ __align__(16) float As2[32][132];
    __shared__ __align__(16) float Bs[32][132];
    const int b  = blockIdx.z;
    const int m0 = blockIdx.y * 64;
    const int p0 = blockIdx.x * 128;
    const float* Xb = X + (size_t)b * xbstride;
    float*       Yb = Y + (size_t)b * ybstride;
    const int tid = threadIdx.x;
    const int tm = tid >> 4, tn = tid & 15;

    // one block zeroes the norm accumulator for this pass
    if (blockIdx.x == 0 && blockIdx.y == 0 && blockIdx.z == 0) {
        for (int i = tid; i < BB * 128 * TT; i += 128) g_norm2[i] = 0.f;
    }

    unsigned long long acc[8][4];
    #pragma unroll
    for (int i = 0; i < 8; i++)
        #pragma unroll
        for (int j = 0; j < 4; j++) acc[i][j] = 0ull;

    for (int kb = 0; kb < 64; kb += 32) {
        #pragma unroll
        for (int j = 0; j < 4; j++) {
            int idx = tid + j * 128;
            int row = idx >> 3;
            int kc  = (idx & 7) * 4;
            float4 w4 = *(const float4*)&W[(size_t)(m0 + row) * 64 + kb + kc];
            *(unsigned long long*)&As2[kc + 0][2 * row] = dup2(w4.x);
            *(unsigned long long*)&As2[kc + 1][2 * row] = dup2(w4.y);
            *(unsigned long long*)&As2[kc + 2][2 * row] = dup2(w4.z);
            *(unsigned long long*)&As2[kc + 3][2 * row] = dup2(w4.w);
        }
        #pragma unroll
        for (int j = 0; j < 8; j++) {
            int idx = tid + j * 128;
            int row = idx >> 5;
            int col = (idx & 31) * 4;
            *(float4*)&Bs[row][col] = *(const float4*)&Xb[(size_t)(kb + row) * THW + p0 + col];
        }
        __syncthreads();
        #pragma unroll 4
        for (int k = 0; k < 32; k++) {
            unsigned long long a[8], bp[4];
            #pragma unroll
            for (int mi = 0; mi < 8; mi++) a[mi] = lds64(&As2[k][2 * (tm * 8 + mi)]);
            #pragma unroll
            for (int u = 0; u < 4; u++)    bp[u] = lds64(&Bs[k][2 * tn + 32 * u]);
            #pragma unroll
            for (int mi = 0; mi < 8; mi++)
                #pragma unroll
                for (int u = 0; u < 4; u++) ffma2(acc[mi][u], a[mi], bp[u]);
        }
        __syncthreads();
    }
    #pragma unroll
    for (int mi = 0; mi < 8; mi++) {
        size_t base = (size_t)(m0 + tm * 8 + mi) * THW + p0 + 2 * tn;
        #pragma unroll
        for (int u = 0; u < 4; u++)
            *(float2*)&Yb[base + 32 * u] = unpk(acc[mi][u]);
    }
}

// ---------------- K2: depthwise 3x3 + temporal mix + fused norm^2 -----------
__global__ __launch_bounds__(256) void dwconv_tmix(
    const float* __restrict__ wdw, const float* __restrict__ wt,
    const float* __restrict__ bt)
{
    __shared__ float tile[TT][18][18];
    const int bc = blockIdx.z;
    const int c  = bc % C3;
    const int h0 = blockIdx.y * 16, w0 = blockIdx.x * 16;
    const float* src = g_qkv0 + (size_t)bc * THW;
    float*       dst = g_qkv1 + (size_t)bc * THW;
    const int tid = threadIdx.x;

    for (int idx = tid; idx < TT * 18 * 18; idx += 256) {
        int t = idx / 324, rem = idx % 324;
        int y = rem / 18, x = rem % 18;
        int gh = h0 + y - 1, gw = w0 + x - 1;
        float v = 0.f;
        if (gh >= 0 && gh < HH && gw >= 0 && gw < WW)
            v = src[(size_t)t * HW + gh * WW + gw];
        tile[t][y][x] = v;
    }
    __syncthreads();

    float wd[9];
    #pragma unroll
    for (int i = 0; i < 9; i++) wd[i] = wdw[c * 9 + i];

    const int y = tid >> 4, x = tid & 15;
    float cv[TT];
    #pragma unroll
    for (int t = 0; t < TT; t++) {
        float s = 0.f;
        #pragma unroll
        for (int kh = 0; kh < 3; kh++)
            #pragma unroll
            for (int kw = 0; kw < 3; kw++)
                s += wd[kh * 3 + kw] * tile[t][y + kh][x + kw];
        cv[t] = s;
    }
    const int hw = (h0 + y) * WW + (w0 + x);
    const bool qk = (c < 128);
    const int b = bc / C3;
    float* np = g_norm2 + (size_t)(b * 128 + c) * TT;
    #pragma unroll
    for (int s = 0; s < TT; s++) {
        float o = bt[s];
        #pragma unroll
        for (int t = 0; t < TT; t++) o += wt[s * TT + t] * cv[t];
        dst[(size_t)s * HW + hw] = o;
        if (qk) {
            float sq = o * o;
            #pragma unroll
            for (int off = 16; off; off >>= 1)
                sq += __shfl_xor_sync(0xffffffffu, sq, off);
            if ((tid & 31) == 0) atomicAdd(&np[s], sq);
        }
    }
}

// ---------------- K3b: S partials = Q K^T -----------------------------------
// 512 threads (4 warps/SMSP), 160x160 tile, micro 5x(5x2) FFMA2, dup-A smem,
// register-prefetch double buffering, split-K = 8.  (round-7 proven form)
#define QAS 330                        // dup-A row stride (floats)
#define QBS 166                        // K row stride (floats)
#define QK_STG (32 * QAS + 32 * QBS)   // one stage, floats

__global__ __launch_bounds__(512, 1) void qk_gemm6()
{
    extern __shared__ __align__(16) float sm[];
    const int bh = blockIdx.x;
    const int ks = blockIdx.y;
    const int b = bh >> 2, h = bh & 3;
    const float* Q  = g_qkv1 + ((size_t)b * C3 + h * CPH) * THW + (size_t)ks * KCH;
    const float* Kp = Q + (size_t)CC * THW;
    const int tid = threadIdx.x;
    const int tm = tid >> 4;            // 0..31 -> rows tm*5..tm*5+4
    const int tn = tid & 15;            // 0..15 -> col pairs 10tn..10tn+9

    int lisK[5], lrow[5], lseg[5];
    #pragma unroll
    for (int j = 0; j < 5; j++) {
        int idx = tid + j * 512;
        lisK[j] = idx >= 1280;
        int l = idx - lisK[j] * 1280;
        lrow[j] = l >> 3;
        lseg[j] = (l & 7) * 4;
    }

    unsigned long long acc[5][5];
    #pragma unroll
    for (int i = 0; i < 5; i++)
        #pragma unroll
        for (int j = 0; j < 5; j++) acc[i][j] = 0ull;

    float4 r[5];
    auto gload = [&](int c) {
        const int kb = c * 32;
        #pragma unroll
        for (int j = 0; j < 5; j++)
            r[j] = *(const float4*)((lisK[j] ? Kp : Q) + (size_t)lrow[j] * DD + kb + lseg[j]);
    };
    auto sstore = [&](int s) {
        float* Qs2 = sm + s * QK_STG;
        float* Ksh = Qs2 + 32 * QAS;
        #pragma unroll
        for (int j = 0; j < 5; j++) {
            if (lisK[j]) {
                Ksh[(lseg[j] + 0) * QBS + lrow[j]] = r[j].x;
                Ksh[(lseg[j] + 1) * QBS + lrow[j]] = r[j].y;
                Ksh[(lseg[j] + 2) * QBS + lrow[j]] = r[j].z;
                Ksh[(lseg[j] + 3) * QBS + lrow[j]] = r[j].w;
            } else {
                *(unsigned long long*)&Qs2[(lseg[j] + 0) * QAS + 2 * lrow[j]] = dup2(r[j].x);
                *(unsigned long long*)&Qs2[(lseg[j] + 1) * QAS + 2 * lrow[j]] = dup2(r[j].y);
                *(unsigned long long*)&Qs2[(lseg[j] + 2) * QAS + 2 * lrow[j]] = dup2(r[j].z);
                *(unsigned long long*)&Qs2[(lseg[j] + 3) * QAS + 2 * lrow[j]] = dup2(r[j].w);
            }
        }
    };

    gload(0);
    sstore(0);
    __syncthreads();

    for (int c = 0; c < 16; c++) {
        if (c < 15) gload(c + 1);
        const float* Qs2 = sm + (c & 1) * QK_STG;
        const float* Ksh = Qs2 + 32 * QAS;
        #pragma unroll 4
        for (int k = 0; k < 32; k++) {
            unsigned long long a[5], bp[5];
            #pragma unroll
            for (int g = 0; g < 5; g++) a[g]  = lds64(&Qs2[k * QAS + 10 * tm + 2 * g]);
            #pragma unroll
            for (int u = 0; u < 5; u++) bp[u] = lds64(&Ksh[k * QBS + 10 * tn + 2 * u]);
            #pragma unroll
            for (int g = 0; g < 5; g++)
                #pragma unroll
                for (int u = 0; u < 5; u++) ffma2(acc[g][u], a[g], bp[u]);
        }
        if (c < 15) sstore((c + 1) & 1);
        __syncthreads();
    }

    float* Sp = g_Spart + ((size_t)ks * BH + bh) * NN * NN;
    #pragma unroll
    for (int g = 0; g < 5; g++) {
        int gi = tm * 5 + g;
        #pragma unroll
        for (int u = 0; u < 5; u++)
            *(float2*)&Sp[(size_t)gi * NN + 10 * tn + 2 * u] = unpk(acc[g][u]);
    }
}

// ---------------- K3c: reduce split-K + norms + scale + softmax -------------
__global__ __launch_bounds__(256) void softmax2(const float* __restrict__ temp)
{
    const int warp = (blockIdx.x * 256 + threadIdx.x) >> 5;
    const int lane = threadIdx.x & 31;
    if (warp >= BH * NN) return;
    const int bh = warp / NN, i = warp % NN;
    const int h = bh & 3, b = bh >> 2;
    const float* nq = g_norm2 + (size_t)(b * 128 + h * CPH) * TT;        // + i
    const float* nk = g_norm2 + (size_t)(b * 128 + 64 + h * CPH) * TT;   // + j
    const float invq = 1.f / fmaxf(sqrtf(nq[i]), 1e-12f);
    const float scale_i = invq * temp[h];
    float vals[5];
    float mx = -1e30f;
    #pragma unroll
    for (int j5 = 0; j5 < 5; j5++) {
        int j = lane + j5 * 32;
        float s = 0.f;
        #pragma unroll
        for (int ks = 0; ks < KSPL; ks++)
            s += g_Spart[(((size_t)ks * BH + bh) * NN + i) * NN + j];
        float invk = 1.f / fmaxf(sqrtf(nk[j]), 1e-12f);
        vals[j5] = s * scale_i * invk;
        mx = fmaxf(mx, vals[j5]);
    }
    #pragma unroll
    for (int off = 16; off; off >>= 1) mx = fmaxf(mx, __shfl_xor_sync(0xffffffffu, mx, off));
    float s = 0.f;
    #pragma unroll
    for (int j5 = 0; j5 < 5; j5++) { vals[j5] = __expf(vals[j5] - mx); s += vals[j5]; }
    #pragma unroll
    for (int off = 16; off; off >>= 1) s += __shfl_xor_sync(0xffffffffu, s, off);
    const float invs = 1.f / s;
    float* row = g_S + (size_t)bh * NN * NN + (size_t)i * NN;
    #pragma unroll
    for (int j5 = 0; j5 < 5; j5++) row[lane + j5 * 32] = vals[j5] * invs;
}

// ---------------- K3d: O = P V ----------------------------------------------
// 256 threads, 2 CTAs/SM, tile 80(i) x 256(d), micro 5x(8x2), cp.async 2-stage.
#define PS 36                          // P row stride (floats)
#define VS 264                         // V row stride (floats)
#define PV_STAGE (80 * PS + 32 * VS)   // floats

__global__ __launch_bounds__(256, 2) void pv_gemm5()
{
    extern __shared__ __align__(16) float sm[];
    const uint32_t sbase = smem_u32(sm);
    const int bh = blockIdx.z;
    const int b = bh >> 2, h = bh & 3;
    const int i0 = blockIdx.y * 80;
    const int d0 = blockIdx.x * 256;
    const float* P = g_S + (size_t)bh * NN * NN;
    const float* V = g_qkv1 + ((size_t)b * C3 + 2 * CC + h * CPH) * THW;
    float*       O = g_O   + ((size_t)b * CC + h * CPH) * THW;
    const int tid = threadIdx.x;
    const int tm = tid >> 4, tn = tid & 15;

    auto copy_chunk = [&](int c, int s) {
        const int kb = c * 32;
        #pragma unroll
        for (int j = 0; j < 3; j++) {
            int idx = tid + j * 256;
            if (idx < 640) {
                int row = idx >> 3, seg = idx & 7;
                cpasync16(sbase + (uint32_t)(s * PV_STAGE + row * PS + seg * 4) * 4u,
                          P + (size_t)(i0 + row) * NN + kb + seg * 4);
            }
        }
        #pragma unroll
        for (int j = 0; j < 8; j++) {
            int idx = tid + j * 256;
            int row = idx >> 6, col = (idx & 63) * 4;
            cpasync16(sbase + (uint32_t)(s * PV_STAGE + 80 * PS + row * VS + col) * 4u,
                      V + (size_t)(kb + row) * DD + d0 + col);
        }
        CP_COMMIT();
    };

    unsigned long long acc[5][8];
    #pragma unroll
    for (int i = 0; i < 5; i++)
        #pragma unroll
        for (int j = 0; j < 8; j++) acc[i][j] = 0ull;

    copy_chunk(0, 0);
    copy_chunk(1, 1);

    for (int c = 0; c < 5; c++) {
        if (c < 4) { CP_WAIT1(); } else { CP_WAIT0(); }
        __syncthreads();
        const float* Ps = sm + (c & 1) * PV_STAGE;
        const float* Vs = Ps + 80 * PS;
        #pragma unroll 4
        for (int k = 0; k < 32; k++) {
            unsigned long long bp[8];
            #pragma unroll
            for (int u = 0; u < 8; u++)
                bp[u] = lds64(&Vs[k * VS + 2 * tn + 32 * u]);
            #pragma unroll
            for (int v = 0; v < 5; v++) {
                unsigned long long a = dup2(Ps[(tm * 5 + v) * PS + k]);
                #pragma unroll
                for (int u = 0; u < 8; u++) ffma2(acc[v][u], a, bp[u]);
            }
        }
        __syncthreads();
        if (c < 3) copy_chunk(c + 2, c & 1);
    }

    #pragma unroll
    for (int v = 0; v < 5; v++) {
        size_t base = (size_t)(i0 + tm * 5 + v) * DD + d0 + 2 * tn;
        #pragma unroll
        for (int u = 0; u < 8; u++)
            *(float2*)&O[base + 32 * u] = unpk(acc[v][u]);
    }
}

// ---------------- host launcher --------------------------------------------
extern "C" void kernel_launch(void* const* d_in, const int* in_sizes, int n_in,
                              void* d_out, int out_size)
{
    const float* x      = (const float*)d_in[0];
    const float* w_qkv  = (const float*)d_in[1];
    const float* w_dw   = (const float*)d_in[2];
    const float* w_t    = (const float*)d_in[3];
    const float* b_t    = (const float*)d_in[4];
    const float* temp   = (const float*)d_in[5];
    const float* w_out  = (const float*)d_in[6];
    float* out = (float*)d_out;

    float *qkv0, *obuf;
    cudaGetSymbolAddress((void**)&qkv0, g_qkv0);
    cudaGetSymbolAddress((void**)&obuf, g_O);

    const int qk_smem = 2 * QK_STG * 4;     // 126976 B
    const int pv_smem = 2 * PV_STAGE * 4;   // 90624 B
    cudaFuncSetAttribute(qk_gemm6, cudaFuncAttributeMaxDynamicSharedMemorySize, qk_smem);
    cudaFuncSetAttribute(pv_gemm5, cudaFuncAttributeMaxDynamicSharedMemorySize, pv_smem);

    // K1: qkv projection (also zeroes g_norm2)
    gemm_proj2<<<dim3(THW / 128, C3 / 64, BB), 128>>>(
        w_qkv, x, qkv0, (long)CC * THW, (long)C3 * THW);

    // K2: depthwise 3x3 + temporal mix + fused norm^2
    dwconv_tmix<<<dim3(4, 4, BB * C3), 256>>>(w_dw, w_t, b_t);

    // K3b: split-K scores (512 threads, 4 warps/SMSP)
    qk_gemm6<<<dim3(BH, KSPL), 512, qk_smem>>>();

    // K3c: reduce + norms + scale + softmax
    softmax2<<<(BH * NN) / 8, 256>>>(temp);

    // K3d: O = P V (2 CTAs/SM, cp.async)
    pv_gemm5<<<dim3(DD / 256, NN / 80, BH), 256, pv_smem>>>();

    // K7: final projection -> d_out
    gemm_proj2<<<dim3(THW / 128, 1, BB), 128>>>(
        w_out, obuf, out, (long)CC * THW, (long)CC * THW);
}

// round 10
// speedup vs baseline: 1.1890x; 1.1284x over previous
#include <cuda_runtime.h>
#include <math.h>
#include <stdint.h>

#define BB 4
#define CC 64
#define C3 192
#define TT 10
#define HH 64
#define WW 64
#define HW 4096
#define THW 40960
#define HEADS 4
#define CPH 16
#define NN 160
#define DD 4096
#define BH (BB*HEADS)
#define KSPL 8
#define KCH (DD/KSPL)   // 512

// ---------------- scratch (device globals) ---------------------------------
__device__ float g_qkv0[(size_t)BB * C3 * THW];
__device__ float g_qkv1[(size_t)BB * C3 * THW];
__device__ float g_Spart[(size_t)KSPL * BH * NN * NN];
__device__ float g_S[(size_t)BH * NN * NN];
__device__ float g_invq[BH * NN];
__device__ float g_invk[BH * NN];
__device__ float g_O[(size_t)BB * CC * THW];

// ---------------- packed f32x2 helpers --------------------------------------
__device__ __forceinline__ void ffma2(unsigned long long& d,
                                      unsigned long long a, unsigned long long b) {
    asm("fma.rn.f32x2 %0, %1, %2, %0;" : "+l"(d) : "l"(a), "l"(b));
}
__device__ __forceinline__ unsigned long long dup2(float x) {
    unsigned long long r;
    asm("mov.b64 %0, {%1, %1};" : "=l"(r) : "f"(x));
    return r;
}
__device__ __forceinline__ float2 unpk(unsigned long long v) {
    float2 r;
    asm("mov.b64 {%0, %1}, %2;" : "=f"(r.x), "=f"(r.y) : "l"(v));
    return r;
}
__device__ __forceinline__ unsigned long long lds64(const float* p) {
    return *(const unsigned long long*)p;
}
__device__ __forceinline__ uint32_t smem_u32(const void* p) {
    uint32_t a;
    asm("{ .reg .u64 t; cvta.to.shared.u64 t, %1; cvt.u32.u64 %0, t; }" : "=r"(a) : "l"(p));
    return a;
}
__device__ __forceinline__ void cpasync16(uint32_t dst, const void* src) {
    asm volatile("cp.async.cg.shared.global [%0], [%1], 16;" :: "r"(dst), "l"(src));
}
#define CP_COMMIT() asm volatile("cp.async.commit_group;" ::: "memory")
#define CP_WAIT1()  asm volatile("cp.async.wait_group 1;" ::: "memory")
#define CP_WAIT0()  asm volatile("cp.async.wait_group 0;" ::: "memory")

// ---------------- K1 / K7: projection GEMM (FFMA2, multi-CTA/SM) ------------
__global__ __launch_bounds__(128) void gemm_proj2(
    const float* __restrict__ W, const float* __restrict__ X, float* __restrict__ Y,
    long xbstride, long ybstride)
{
    __shared__ __align__(16) float As2[32][132];
    __shared__ __align__(16) float Bs[32][132];
    const int b  = blockIdx.z;
    const int m0 = blockIdx.y * 64;
    const int p0 = blockIdx.x * 128;
    const float* Xb = X + (size_t)b * xbstride;
    float*       Yb = Y + (size_t)b * ybstride;
    const int tid = threadIdx.x;
    const int tm = tid >> 4, tn = tid & 15;

    unsigned long long acc[8][4];
    #pragma unroll
    for (int i = 0; i < 8; i++)
        #pragma unroll
        for (int j = 0; j < 4; j++) acc[i][j] = 0ull;

    for (int kb = 0; kb < 64; kb += 32) {
        #pragma unroll
        for (int j = 0; j < 4; j++) {
            int idx = tid + j * 128;
            int row = idx >> 3;
            int kc  = (idx & 7) * 4;
            float4 w4 = *(const float4*)&W[(size_t)(m0 + row) * 64 + kb + kc];
            *(unsigned long long*)&As2[kc + 0][2 * row] = dup2(w4.x);
            *(unsigned long long*)&As2[kc + 1][2 * row] = dup2(w4.y);
            *(unsigned long long*)&As2[kc + 2][2 * row] = dup2(w4.z);
            *(unsigned long long*)&As2[kc + 3][2 * row] = dup2(w4.w);
        }
        #pragma unroll
        for (int j = 0; j < 8; j++) {
            int idx = tid + j * 128;
            int row = idx >> 5;
            int col = (idx & 31) * 4;
            *(float4*)&Bs[row][col] = *(const float4*)&Xb[(size_t)(kb + row) * THW + p0 + col];
        }
        __syncthreads();
        #pragma unroll 4
        for (int k = 0; k < 32; k++) {
            unsigned long long a[8], bp[4];
            #pragma unroll
            for (int mi = 0; mi < 8; mi++) a[mi] = lds64(&As2[k][2 * (tm * 8 + mi)]);
            #pragma unroll
            for (int u = 0; u < 4; u++)    bp[u] = lds64(&Bs[k][2 * tn + 32 * u]);
            #pragma unroll
            for (int mi = 0; mi < 8; mi++)
                #pragma unroll
                for (int u = 0; u < 4; u++) ffma2(acc[mi][u], a[mi], bp[u]);
        }
        __syncthreads();
    }
    #pragma unroll
    for (int mi = 0; mi < 8; mi++) {
        size_t base = (size_t)(m0 + tm * 8 + mi) * THW + p0 + 2 * tn;
        #pragma unroll
        for (int u = 0; u < 4; u++)
            *(float2*)&Yb[base + 32 * u] = unpk(acc[mi][u]);
    }
}

// ---------------- K2: depthwise 3x3 + temporal mix, 16x64 strips -------------
// grid: (4 h-strips, BB*C3). 256 threads; each thread does 4 px along w.
__global__ __launch_bounds__(256) void dwconv_tmix3(
    const float* __restrict__ wdw, const float* __restrict__ wt,
    const float* __restrict__ bt)
{
    __shared__ __align__(16) float tile[TT][18][68];
    __shared__ float wts[TT * TT + TT];
    const int bc = blockIdx.y;
    const int c  = bc % C3;
    const int h0 = blockIdx.x * 16;
    const float* src = g_qkv0 + (size_t)bc * THW;
    float*       dst = g_qkv1 + (size_t)bc * THW;
    const int tid = threadIdx.x;

    if (tid < TT * TT + TT)
        wts[tid] = (tid < TT * TT) ? wt[tid] : bt[tid - TT * TT];

    // halo load: 10 t x 18 rows x 66 cols (coalesced 66-float rows)
    for (int idx = tid; idx < TT * 18 * 66; idx += 256) {
        int t = idx / (18 * 66);
        int rem = idx % (18 * 66);
        int y = rem / 66, x = rem % 66;
        int gh = h0 + y - 1, gw = x - 1;
        float v = 0.f;
        if (gh >= 0 && gh < HH && gw >= 0 && gw < WW)
            v = src[(size_t)t * HW + gh * WW + gw];
        tile[t][y][x] = v;
    }
    __syncthreads();

    float wd[9];
    #pragma unroll
    for (int i = 0; i < 9; i++) wd[i] = wdw[c * 9 + i];

    const int y  = tid >> 4;          // 0..15
    const int x0 = (tid & 15) * 4;    // 0..60 (4-aligned)

    float cv[4][TT];
    #pragma unroll
    for (int xx = 0; xx < 4; xx++)
        #pragma unroll
        for (int t = 0; t < TT; t++) cv[xx][t] = 0.f;

    #pragma unroll
    for (int t = 0; t < TT; t++) {
        #pragma unroll
        for (int kh = 0; kh < 3; kh++) {
            const float* row = &tile[t][y + kh][x0];
            float4 q = *(const float4*)row;
            float2 r2 = *(const float2*)(row + 4);
            float w0 = wd[kh * 3], w1 = wd[kh * 3 + 1], w2 = wd[kh * 3 + 2];
            cv[0][t] += w0 * q.x + w1 * q.y  + w2 * q.z;
            cv[1][t] += w0 * q.y + w1 * q.z  + w2 * q.w;
            cv[2][t] += w0 * q.z + w1 * q.w  + w2 * r2.x;
            cv[3][t] += w0 * q.w + w1 * r2.x + w2 * r2.y;
        }
    }

    const int hw = (h0 + y) * WW + x0;
    #pragma unroll
    for (int s = 0; s < TT; s++) {
        float bs = wts[TT * TT + s];
        float4 o = make_float4(bs, bs, bs, bs);
        #pragma unroll
        for (int t = 0; t < TT; t++) {
            float w = wts[s * TT + t];
            o.x += w * cv[0][t];
            o.y += w * cv[1][t];
            o.z += w * cv[2][t];
            o.w += w * cv[3][t];
        }
        *(float4*)&dst[(size_t)s * HW + hw] = o;
    }
}

// ---------------- K3a: L2 norms of q/k rows ---------------------------------
__global__ __launch_bounds__(256) void norms_kernel()
{
    const int warp = (blockIdx.x * 256 + threadIdx.x) >> 5;
    const int lane = threadIdx.x & 31;
    if (warp >= 2 * BH * NN) return;
    const int qk = warp / (BH * NN);
    const int r  = warp % (BH * NN);
    const int bh = r / NN, i = r % NN;
    const int b = bh / HEADS, h = bh % HEADS;
    const float* row = g_qkv1 + ((size_t)b * C3 + qk * CC + h * CPH) * THW + (size_t)i * DD;
    float s = 0.f;
    for (int d = lane * 4; d < DD; d += 128) {
        float4 v = *(const float4*)&row[d];
        s += v.x * v.x + v.y * v.y + v.z * v.z + v.w * v.w;
    }
    #pragma unroll
    for (int off = 16; off; off >>= 1) s += __shfl_xor_sync(0xffffffffu, s, off);
    if (lane == 0) {
        float inv = 1.f / fmaxf(sqrtf(s), 1e-12f);
        (qk ? g_invk : g_invq)[bh * NN + i] = inv;
    }
}

// ---------------- K3b: S partials = Q K^T -----------------------------------
// 512 threads (4 warps/SMSP), 160x160 tile, micro 5x(5x2) FFMA2, dup-A smem,
// register-prefetch double buffering, split-K = 8.  (round-7 proven form)
#define QAS 330                        // dup-A row stride (floats)
#define QBS 166                        // K row stride (floats)
#define QK_STG (32 * QAS + 32 * QBS)   // one stage, floats

__global__ __launch_bounds__(512, 1) void qk_gemm6()
{
    extern __shared__ __align__(16) float sm[];
    const int bh = blockIdx.x;
    const int ks = blockIdx.y;
    const int b = bh >> 2, h = bh & 3;
    const float* Q  = g_qkv1 + ((size_t)b * C3 + h * CPH) * THW + (size_t)ks * KCH;
    const float* Kp = Q + (size_t)CC * THW;
    const int tid = threadIdx.x;
    const int tm = tid >> 4;            // 0..31 -> rows tm*5..tm*5+4
    const int tn = tid & 15;            // 0..15 -> col pairs 10tn..10tn+9

    int lisK[5], lrow[5], lseg[5];
    #pragma unroll
    for (int j = 0; j < 5; j++) {
        int idx = tid + j * 512;
        lisK[j] = idx >= 1280;
        int l = idx - lisK[j] * 1280;
        lrow[j] = l >> 3;
        lseg[j] = (l & 7) * 4;
    }

    unsigned long long acc[5][5];
    #pragma unroll
    for (int i = 0; i < 5; i++)
        #pragma unroll
        for (int j = 0; j < 5; j++) acc[i][j] = 0ull;

    float4 r[5];
    auto gload = [&](int c) {
        const int kb = c * 32;
        #pragma unroll
        for (int j = 0; j < 5; j++)
            r[j] = *(const float4*)((lisK[j] ? Kp : Q) + (size_t)lrow[j] * DD + kb + lseg[j]);
    };
    auto sstore = [&](int s) {
        float* Qs2 = sm + s * QK_STG;
        float* Ksh = Qs2 + 32 * QAS;
        #pragma unroll
        for (int j = 0; j < 5; j++) {
            if (lisK[j]) {
                Ksh[(lseg[j] + 0) * QBS + lrow[j]] = r[j].x;
                Ksh[(lseg[j] + 1) * QBS + lrow[j]] = r[j].y;
                Ksh[(lseg[j] + 2) * QBS + lrow[j]] = r[j].z;
                Ksh[(lseg[j] + 3) * QBS + lrow[j]] = r[j].w;
            } else {
                *(unsigned long long*)&Qs2[(lseg[j] + 0) * QAS + 2 * lrow[j]] = dup2(r[j].x);
                *(unsigned long long*)&Qs2[(lseg[j] + 1) * QAS + 2 * lrow[j]] = dup2(r[j].y);
                *(unsigned long long*)&Qs2[(lseg[j] + 2) * QAS + 2 * lrow[j]] = dup2(r[j].z);
                *(unsigned long long*)&Qs2[(lseg[j] + 3) * QAS + 2 * lrow[j]] = dup2(r[j].w);
            }
        }
    };

    gload(0);
    sstore(0);
    __syncthreads();

    for (int c = 0; c < 16; c++) {
        if (c < 15) gload(c + 1);
        const float* Qs2 = sm + (c & 1) * QK_STG;
        const float* Ksh = Qs2 + 32 * QAS;
        #pragma unroll 4
        for (int k = 0; k < 32; k++) {
            unsigned long long a[5], bp[5];
            #pragma unroll
            for (int g = 0; g < 5; g++) a[g]  = lds64(&Qs2[k * QAS + 10 * tm + 2 * g]);
            #pragma unroll
            for (int u = 0; u < 5; u++) bp[u] = lds64(&Ksh[k * QBS + 10 * tn + 2 * u]);
            #pragma unroll
            for (int g = 0; g < 5; g++)
                #pragma unroll
                for (int u = 0; u < 5; u++) ffma2(acc[g][u], a[g], bp[u]);
        }
        if (c < 15) sstore((c + 1) & 1);
        __syncthreads();
    }

    float* Sp = g_Spart + ((size_t)ks * BH + bh) * NN * NN;
    #pragma unroll
    for (int g = 0; g < 5; g++) {
        int gi = tm * 5 + g;
        #pragma unroll
        for (int u = 0; u < 5; u++)
            *(float2*)&Sp[(size_t)gi * NN + 10 * tn + 2 * u] = unpk(acc[g][u]);
    }
}

// ---------------- K3c: reduce split-K + scale + softmax ---------------------
__global__ __launch_bounds__(256) void softmax2(const float* __restrict__ temp)
{
    const int warp = (blockIdx.x * 256 + threadIdx.x) >> 5;
    const int lane = threadIdx.x & 31;
    if (warp >= BH * NN) return;
    const int bh = warp / NN, i = warp % NN;
    const int h = bh & 3;
    const float scale_i = g_invq[bh * NN + i] * temp[h];
    float vals[5];
    float mx = -1e30f;
    #pragma unroll
    for (int j5 = 0; j5 < 5; j5++) {
        int j = lane + j5 * 32;
        float s = 0.f;
        #pragma unroll
        for (int ks = 0; ks < KSPL; ks++)
            s += g_Spart[(((size_t)ks * BH + bh) * NN + i) * NN + j];
        vals[j5] = s * scale_i * g_invk[bh * NN + j];
        mx = fmaxf(mx, vals[j5]);
    }
    #pragma unroll
    for (int off = 16; off; off >>= 1) mx = fmaxf(mx, __shfl_xor_sync(0xffffffffu, mx, off));
    float s = 0.f;
    #pragma unroll
    for (int j5 = 0; j5 < 5; j5++) { vals[j5] = __expf(vals[j5] - mx); s += vals[j5]; }
    #pragma unroll
    for (int off = 16; off; off >>= 1) s += __shfl_xor_sync(0xffffffffu, s, off);
    const float invs = 1.f / s;
    float* row = g_S + (size_t)bh * NN * NN + (size_t)i * NN;
    #pragma unroll
    for (int j5 = 0; j5 < 5; j5++) row[lane + j5 * 32] = vals[j5] * invs;
}

// ---------------- K3d: O = P V ----------------------------------------------
// 256 threads, 2 CTAs/SM, tile 80(i) x 256(d), micro 5x(8x2), cp.async 2-stage.
#define PS 36                          // P row stride (floats)
#define VS 264                         // V row stride (floats)
#define PV_STAGE (80 * PS + 32 * VS)   // floats

__global__ __launch_bounds__(256, 2) void pv_gemm5()
{
    extern __shared__ __align__(16) float sm[];
    const uint32_t sbase = smem_u32(sm);
    const int bh = blockIdx.z;
    const int b = bh >> 2, h = bh & 3;
    const int i0 = blockIdx.y * 80;
    const int d0 = blockIdx.x * 256;
    const float* P = g_S + (size_t)bh * NN * NN;
    const float* V = g_qkv1 + ((size_t)b * C3 + 2 * CC + h * CPH) * THW;
    float*       O = g_O   + ((size_t)b * CC + h * CPH) * THW;
    const int tid = threadIdx.x;
    const int tm = tid >> 4, tn = tid & 15;

    auto copy_chunk = [&](int c, int s) {
        const int kb = c * 32;
        #pragma unroll
        for (int j = 0; j < 3; j++) {
            int idx = tid + j * 256;
            if (idx < 640) {
                int row = idx >> 3, seg = idx & 7;
                cpasync16(sbase + (uint32_t)(s * PV_STAGE + row * PS + seg * 4) * 4u,
                          P + (size_t)(i0 + row) * NN + kb + seg * 4);
            }
        }
        #pragma unroll
        for (int j = 0; j < 8; j++) {
            int idx = tid + j * 256;
            int row = idx >> 6, col = (idx & 63) * 4;
            cpasync16(sbase + (uint32_t)(s * PV_STAGE + 80 * PS + row * VS + col) * 4u,
                      V + (size_t)(kb + row) * DD + d0 + col);
        }
        CP_COMMIT();
    };

    unsigned long long acc[5][8];
    #pragma unroll
    for (int i = 0; i < 5; i++)
        #pragma unroll
        for (int j = 0; j < 8; j++) acc[i][j] = 0ull;

    copy_chunk(0, 0);
    copy_chunk(1, 1);

    for (int c = 0; c < 5; c++) {
        if (c < 4) { CP_WAIT1(); } else { CP_WAIT0(); }
        __syncthreads();
        const float* Ps = sm + (c & 1) * PV_STAGE;
        const float* Vs = Ps + 80 * PS;
        #pragma unroll 4
        for (int k = 0; k < 32; k++) {
            unsigned long long bp[8];
            #pragma unroll
            for (int u = 0; u < 8; u++)
                bp[u] = lds64(&Vs[k * VS + 2 * tn + 32 * u]);
            #pragma unroll
            for (int v = 0; v < 5; v++) {
                unsigned long long a = dup2(Ps[(tm * 5 + v) * PS + k]);
                #pragma unroll
                for (int u = 0; u < 8; u++) ffma2(acc[v][u], a, bp[u]);
            }
        }
        __syncthreads();
        if (c < 3) copy_chunk(c + 2, c & 1);
    }

    #pragma unroll
    for (int v = 0; v < 5; v++) {
        size_t base = (size_t)(i0 + tm * 5 + v) * DD + d0 + 2 * tn;
        #pragma unroll
        for (int u = 0; u < 8; u++)
            *(float2*)&O[base + 32 * u] = unpk(acc[v][u]);
    }
}

// ---------------- host launcher --------------------------------------------
extern "C" void kernel_launch(void* const* d_in, const int* in_sizes, int n_in,
                              void* d_out, int out_size)
{
    const float* x      = (const float*)d_in[0];
    const float* w_qkv  = (const float*)d_in[1];
    const float* w_dw   = (const float*)d_in[2];
    const float* w_t    = (const float*)d_in[3];
    const float* b_t    = (const float*)d_in[4];
    const float* temp   = (const float*)d_in[5];
    const float* w_out  = (const float*)d_in[6];
    float* out = (float*)d_out;

    float *qkv0, *obuf;
    cudaGetSymbolAddress((void**)&qkv0, g_qkv0);
    cudaGetSymbolAddress((void**)&obuf, g_O);

    const int qk_smem = 2 * QK_STG * 4;     // 126976 B
    const int pv_smem = 2 * PV_STAGE * 4;   // 90624 B
    cudaFuncSetAttribute(qk_gemm6, cudaFuncAttributeMaxDynamicSharedMemorySize, qk_smem);
    cudaFuncSetAttribute(pv_gemm5, cudaFuncAttributeMaxDynamicSharedMemorySize, pv_smem);

    // K1: qkv projection (192 x 40960 per batch)
    gemm_proj2<<<dim3(THW / 128, C3 / 64, BB), 128>>>(
        w_qkv, x, qkv0, (long)CC * THW, (long)C3 * THW);

    // K2: depthwise 3x3 + temporal mix (16x64 strips, coalesced)
    dwconv_tmix3<<<dim3(4, BB * C3), 256>>>(w_dw, w_t, b_t);

    // K3a: q/k row norms
    norms_kernel<<<640, 256>>>();

    // K3b: split-K scores (512 threads, 4 warps/SMSP)
    qk_gemm6<<<dim3(BH, KSPL), 512, qk_smem>>>();

    // K3c: reduce + scale + softmax
    softmax2<<<(BH * NN) / 8, 256>>>(temp);

    // K3d: O = P V (2 CTAs/SM, cp.async)
    pv_gemm5<<<dim3(DD / 256, NN / 80, BH), 256, pv_smem>>>();

    // K7: final projection -> d_out
    gemm_proj2<<<dim3(THW / 128, 1, BB), 128>>>(
        w_out, obuf, out, (long)CC * THW, (long)CC * THW);
}

// round 11
// speedup vs baseline: 1.2044x; 1.0129x over previous
#include <cuda_runtime.h>
#include <math.h>
#include <stdint.h>

#define BB 4
#define CC 64
#define C3 192
#define TT 10
#define HH 64
#define WW 64
#define HW 4096
#define THW 40960
#define HEADS 4
#define CPH 16
#define NN 160
#define DD 4096
#define BH (BB*HEADS)
#define KSPL 8
#define KCH (DD/KSPL)   // 512

// ---------------- scratch (device globals) ---------------------------------
__device__ float g_qkv0[(size_t)BB * C3 * THW];
__device__ float g_qkv1[(size_t)BB * C3 * THW];
__device__ float g_Spart[(size_t)KSPL * BH * NN * NN];
__device__ float g_S[(size_t)BH * NN * NN];
__device__ float g_invq[BH * NN];
__device__ float g_invk[BH * NN];
__device__ float g_O[(size_t)BB * CC * THW];

// ---------------- packed f32x2 helpers --------------------------------------
__device__ __forceinline__ void ffma2(unsigned long long& d,
                                      unsigned long long a, unsigned long long b) {
    asm("fma.rn.f32x2 %0, %1, %2, %0;" : "+l"(d) : "l"(a), "l"(b));
}
__device__ __forceinline__ unsigned long long dup2(float x) {
    unsigned long long r;
    asm("mov.b64 %0, {%1, %1};" : "=l"(r) : "f"(x));
    return r;
}
__device__ __forceinline__ float2 unpk(unsigned long long v) {
    float2 r;
    asm("mov.b64 {%0, %1}, %2;" : "=f"(r.x), "=f"(r.y) : "l"(v));
    return r;
}
__device__ __forceinline__ unsigned long long lds64(const float* p) {
    return *(const unsigned long long*)p;
}
__device__ __forceinline__ uint32_t smem_u32(const void* p) {
    uint32_t a;
    asm("{ .reg .u64 t; cvta.to.shared.u64 t, %1; cvt.u32.u64 %0, t; }" : "=r"(a) : "l"(p));
    return a;
}
__device__ __forceinline__ void cpasync16(uint32_t dst, const void* src) {
    asm volatile("cp.async.cg.shared.global [%0], [%1], 16;" :: "r"(dst), "l"(src));
}
#define CP_COMMIT() asm volatile("cp.async.commit_group;" ::: "memory")
#define CP_WAIT1()  asm volatile("cp.async.wait_group 1;" ::: "memory")
#define CP_WAIT0()  asm volatile("cp.async.wait_group 0;" ::: "memory")

// ---------------- K1 / K7: projection GEMM (FFMA2, multi-CTA/SM) ------------
__global__ __launch_bounds__(128) void gemm_proj2(
    const float* __restrict__ W, const float* __restrict__ X, float* __restrict__ Y,
    long xbstride, long ybstride)
{
    __shared__ __align__(16) float As2[32][132];
    __shared__ __align__(16) float Bs[32][132];
    const int b  = blockIdx.z;
    const int m0 = blockIdx.y * 64;
    const int p0 = blockIdx.x * 128;
    const float* Xb = X + (size_t)b * xbstride;
    float*       Yb = Y + (size_t)b * ybstride;
    const int tid = threadIdx.x;
    const int tm = tid >> 4, tn = tid & 15;

    unsigned long long acc[8][4];
    #pragma unroll
    for (int i = 0; i < 8; i++)
        #pragma unroll
        for (int j = 0; j < 4; j++) acc[i][j] = 0ull;

    for (int kb = 0; kb < 64; kb += 32) {
        #pragma unroll
        for (int j = 0; j < 4; j++) {
            int idx = tid + j * 128;
            int row = idx >> 3;
            int kc  = (idx & 7) * 4;
            float4 w4 = *(const float4*)&W[(size_t)(m0 + row) * 64 + kb + kc];
            *(unsigned long long*)&As2[kc + 0][2 * row] = dup2(w4.x);
            *(unsigned long long*)&As2[kc + 1][2 * row] = dup2(w4.y);
            *(unsigned long long*)&As2[kc + 2][2 * row] = dup2(w4.z);
            *(unsigned long long*)&As2[kc + 3][2 * row] = dup2(w4.w);
        }
        #pragma unroll
        for (int j = 0; j < 8; j++) {
            int idx = tid + j * 128;
            int row = idx >> 5;
            int col = (idx & 31) * 4;
            *(float4*)&Bs[row][col] = *(const float4*)&Xb[(size_t)(kb + row) * THW + p0 + col];
        }
        __syncthreads();
        #pragma unroll 4
        for (int k = 0; k < 32; k++) {
            unsigned long long a[8], bp[4];
            #pragma unroll
            for (int mi = 0; mi < 8; mi++) a[mi] = lds64(&As2[k][2 * (tm * 8 + mi)]);
            #pragma unroll
            for (int u = 0; u < 4; u++)    bp[u] = lds64(&Bs[k][2 * tn + 32 * u]);
            #pragma unroll
            for (int mi = 0; mi < 8; mi++)
                #pragma unroll
                for (int u = 0; u < 4; u++) ffma2(acc[mi][u], a[mi], bp[u]);
        }
        __syncthreads();
    }
    #pragma unroll
    for (int mi = 0; mi < 8; mi++) {
        size_t base = (size_t)(m0 + tm * 8 + mi) * THW + p0 + 2 * tn;
        #pragma unroll
        for (int u = 0; u < 4; u++)
            *(float2*)&Yb[base + 32 * u] = unpk(acc[mi][u]);
    }
}

// ---------------- K2: depthwise 3x3 + temporal mix, 16x64 strips -------------
__global__ __launch_bounds__(256) void dwconv_tmix3(
    const float* __restrict__ wdw, const float* __restrict__ wt,
    const float* __restrict__ bt)
{
    __shared__ __align__(16) float tile[TT][18][68];
    __shared__ float wts[TT * TT + TT];
    const int bc = blockIdx.y;
    const int c  = bc % C3;
    const int h0 = blockIdx.x * 16;
    const float* src = g_qkv0 + (size_t)bc * THW;
    float*       dst = g_qkv1 + (size_t)bc * THW;
    const int tid = threadIdx.x;

    if (tid < TT * TT + TT)
        wts[tid] = (tid < TT * TT) ? wt[tid] : bt[tid - TT * TT];

    for (int idx = tid; idx < TT * 18 * 66; idx += 256) {
        int t = idx / (18 * 66);
        int rem = idx % (18 * 66);
        int y = rem / 66, x = rem % 66;
        int gh = h0 + y - 1, gw = x - 1;
        float v = 0.f;
        if (gh >= 0 && gh < HH && gw >= 0 && gw < WW)
            v = src[(size_t)t * HW + gh * WW + gw];
        tile[t][y][x] = v;
    }
    __syncthreads();

    float wd[9];
    #pragma unroll
    for (int i = 0; i < 9; i++) wd[i] = wdw[c * 9 + i];

    const int y  = tid >> 4;
    const int x0 = (tid & 15) * 4;

    float cv[4][TT];
    #pragma unroll
    for (int xx = 0; xx < 4; xx++)
        #pragma unroll
        for (int t = 0; t < TT; t++) cv[xx][t] = 0.f;

    #pragma unroll
    for (int t = 0; t < TT; t++) {
        #pragma unroll
        for (int kh = 0; kh < 3; kh++) {
            const float* row = &tile[t][y + kh][x0];
            float4 q = *(const float4*)row;
            float2 r2 = *(const float2*)(row + 4);
            float w0 = wd[kh * 3], w1 = wd[kh * 3 + 1], w2 = wd[kh * 3 + 2];
            cv[0][t] += w0 * q.x + w1 * q.y  + w2 * q.z;
            cv[1][t] += w0 * q.y + w1 * q.z  + w2 * q.w;
            cv[2][t] += w0 * q.z + w1 * q.w  + w2 * r2.x;
            cv[3][t] += w0 * q.w + w1 * r2.x + w2 * r2.y;
        }
    }

    const int hw = (h0 + y) * WW + x0;
    #pragma unroll
    for (int s = 0; s < TT; s++) {
        float bs = wts[TT * TT + s];
        float4 o = make_float4(bs, bs, bs, bs);
        #pragma unroll
        for (int t = 0; t < TT; t++) {
            float w = wts[s * TT + t];
            o.x += w * cv[0][t];
            o.y += w * cv[1][t];
            o.z += w * cv[2][t];
            o.w += w * cv[3][t];
        }
        *(float4*)&dst[(size_t)s * HW + hw] = o;
    }
}

// ---------------- K3a: L2 norms of q/k rows ---------------------------------
__global__ __launch_bounds__(256) void norms_kernel()
{
    const int warp = (blockIdx.x * 256 + threadIdx.x) >> 5;
    const int lane = threadIdx.x & 31;
    if (warp >= 2 * BH * NN) return;
    const int qk = warp / (BH * NN);
    const int r  = warp % (BH * NN);
    const int bh = r / NN, i = r % NN;
    const int b = bh / HEADS, h = bh % HEADS;
    const float* row = g_qkv1 + ((size_t)b * C3 + qk * CC + h * CPH) * THW + (size_t)i * DD;
    float s = 0.f;
    for (int d = lane * 4; d < DD; d += 128) {
        float4 v = *(const float4*)&row[d];
        s += v.x * v.x + v.y * v.y + v.z * v.z + v.w * v.w;
    }
    #pragma unroll
    for (int off = 16; off; off >>= 1) s += __shfl_xor_sync(0xffffffffu, s, off);
    if (lane == 0) {
        float inv = 1.f / fmaxf(sqrtf(s), 1e-12f);
        (qk ? g_invk : g_invq)[bh * NN + i] = inv;
    }
}

// ---------------- K3b: S partials = Q K^T -----------------------------------
// 512 threads, 160x160 tile, micro 5x(5x2) FFMA2, dup-A smem, interleaved B
// columns (j = 2*tn + 32*u -> conflict-free LDS.64), reg-prefetch dbuf, KSPL 8.
#define QAS 330                        // dup-A row stride (floats)
#define QBS 166                        // K row stride (floats)
#define QK_STG (32 * QAS + 32 * QBS)   // one stage, floats

__global__ __launch_bounds__(512, 1) void qk_gemm7()
{
    extern __shared__ __align__(16) float sm[];
    const int bh = blockIdx.x;
    const int ks = blockIdx.y;
    const int b = bh >> 2, h = bh & 3;
    const float* Q  = g_qkv1 + ((size_t)b * C3 + h * CPH) * THW + (size_t)ks * KCH;
    const float* Kp = Q + (size_t)CC * THW;
    const int tid = threadIdx.x;
    const int tm = tid >> 4;            // 0..31 -> rows tm*5..tm*5+4
    const int tn = tid & 15;            // col pairs j = 2*tn + 32*u

    int lisK[5], lrow[5], lseg[5];
    #pragma unroll
    for (int j = 0; j < 5; j++) {
        int idx = tid + j * 512;
        lisK[j] = idx >= 1280;
        int l = idx - lisK[j] * 1280;
        lrow[j] = l >> 3;
        lseg[j] = (l & 7) * 4;
    }

    unsigned long long acc[5][5];
    #pragma unroll
    for (int i = 0; i < 5; i++)
        #pragma unroll
        for (int j = 0; j < 5; j++) acc[i][j] = 0ull;

    float4 r[5];
    auto gload = [&](int c) {
        const int kb = c * 32;
        #pragma unroll
        for (int j = 0; j < 5; j++)
            r[j] = *(const float4*)((lisK[j] ? Kp : Q) + (size_t)lrow[j] * DD + kb + lseg[j]);
    };
    auto sstore = [&](int s) {
        float* Qs2 = sm + s * QK_STG;
        float* Ksh = Qs2 + 32 * QAS;
        #pragma unroll
        for (int j = 0; j < 5; j++) {
            if (lisK[j]) {
                Ksh[(lseg[j] + 0) * QBS + lrow[j]] = r[j].x;
                Ksh[(lseg[j] + 1) * QBS + lrow[j]] = r[j].y;
                Ksh[(lseg[j] + 2) * QBS + lrow[j]] = r[j].z;
                Ksh[(lseg[j] + 3) * QBS + lrow[j]] = r[j].w;
            } else {
                *(unsigned long long*)&Qs2[(lseg[j] + 0) * QAS + 2 * lrow[j]] = dup2(r[j].x);
                *(unsigned long long*)&Qs2[(lseg[j] + 1) * QAS + 2 * lrow[j]] = dup2(r[j].y);
                *(unsigned long long*)&Qs2[(lseg[j] + 2) * QAS + 2 * lrow[j]] = dup2(r[j].z);
                *(unsigned long long*)&Qs2[(lseg[j] + 3) * QAS + 2 * lrow[j]] = dup2(r[j].w);
            }
        }
    };

    gload(0);
    sstore(0);
    __syncthreads();

    for (int c = 0; c < 16; c++) {
        if (c < 15) gload(c + 1);
        const float* Qs2 = sm + (c & 1) * QK_STG;
        const float* Ksh = Qs2 + 32 * QAS;
        #pragma unroll 4
        for (int k = 0; k < 32; k++) {
            unsigned long long a[5], bp[5];
            #pragma unroll
            for (int g = 0; g < 5; g++) a[g]  = lds64(&Qs2[k * QAS + 10 * tm + 2 * g]);
            #pragma unroll
            for (int u = 0; u < 5; u++) bp[u] = lds64(&Ksh[k * QBS + 2 * tn + 32 * u]);
            #pragma unroll
            for (int g = 0; g < 5; g++)
                #pragma unroll
                for (int u = 0; u < 5; u++) ffma2(acc[g][u], a[g], bp[u]);
        }
        if (c < 15) sstore((c + 1) & 1);
        __syncthreads();
    }

    float* Sp = g_Spart + ((size_t)ks * BH + bh) * NN * NN;
    #pragma unroll
    for (int g = 0; g < 5; g++) {
        int gi = tm * 5 + g;
        #pragma unroll
        for (int u = 0; u < 5; u++)
            *(float2*)&Sp[(size_t)gi * NN + 2 * tn + 32 * u] = unpk(acc[g][u]);
    }
}

// ---------------- K3c: reduce split-K + scale + softmax ---------------------
__global__ __launch_bounds__(256) void softmax2(const float* __restrict__ temp)
{
    const int warp = (blockIdx.x * 256 + threadIdx.x) >> 5;
    const int lane = threadIdx.x & 31;
    if (warp >= BH * NN) return;
    const int bh = warp / NN, i = warp % NN;
    const int h = bh & 3;
    const float scale_i = g_invq[bh * NN + i] * temp[h];
    float vals[5];
    float mx = -1e30f;
    #pragma unroll
    for (int j5 = 0; j5 < 5; j5++) {
        int j = lane + j5 * 32;
        float s = 0.f;
        #pragma unroll
        for (int ks = 0; ks < KSPL; ks++)
            s += g_Spart[(((size_t)ks * BH + bh) * NN + i) * NN + j];
        vals[j5] = s * scale_i * g_invk[bh * NN + j];
        mx = fmaxf(mx, vals[j5]);
    }
    #pragma unroll
    for (int off = 16; off; off >>= 1) mx = fmaxf(mx, __shfl_xor_sync(0xffffffffu, mx, off));
    float s = 0.f;
    #pragma unroll
    for (int j5 = 0; j5 < 5; j5++) { vals[j5] = __expf(vals[j5] - mx); s += vals[j5]; }
    #pragma unroll
    for (int off = 16; off; off >>= 1) s += __shfl_xor_sync(0xffffffffu, s, off);
    const float invs = 1.f / s;
    float* row = g_S + (size_t)bh * NN * NN + (size_t)i * NN;
    #pragma unroll
    for (int j5 = 0; j5 < 5; j5++) row[lane + j5 * 32] = vals[j5] * invs;
}

// ---------------- K3d: O = P V ----------------------------------------------
#define PS 36                          // P row stride (floats)
#define VS 264                         // V row stride (floats)
#define PV_STAGE (80 * PS + 32 * VS)   // floats

__global__ __launch_bounds__(256, 2) void pv_gemm5()
{
    extern __shared__ __align__(16) float sm[];
    const uint32_t sbase = smem_u32(sm);
    const int bh = blockIdx.z;
    const int b = bh >> 2, h = bh & 3;
    const int i0 = blockIdx.y * 80;
    const int d0 = blockIdx.x * 256;
    const float* P = g_S + (size_t)bh * NN * NN;
    const float* V = g_qkv1 + ((size_t)b * C3 + 2 * CC + h * CPH) * THW;
    float*       O = g_O   + ((size_t)b * CC + h * CPH) * THW;
    const int tid = threadIdx.x;
    const int tm = tid >> 4, tn = tid & 15;

    auto copy_chunk = [&](int c, int s) {
        const int kb = c * 32;
        #pragma unroll
        for (int j = 0; j < 3; j++) {
            int idx = tid + j * 256;
            if (idx < 640) {
                int row = idx >> 3, seg = idx & 7;
                cpasync16(sbase + (uint32_t)(s * PV_STAGE + row * PS + seg * 4) * 4u,
                          P + (size_t)(i0 + row) * NN + kb + seg * 4);
            }
        }
        #pragma unroll
        for (int j = 0; j < 8; j++) {
            int idx = tid + j * 256;
            int row = idx >> 6, col = (idx & 63) * 4;
            cpasync16(sbase + (uint32_t)(s * PV_STAGE + 80 * PS + row * VS + col) * 4u,
                      V + (size_t)(kb + row) * DD + d0 + col);
        }
        CP_COMMIT();
    };

    unsigned long long acc[5][8];
    #pragma unroll
    for (int i = 0; i < 5; i++)
        #pragma unroll
        for (int j = 0; j < 8; j++) acc[i][j] = 0ull;

    copy_chunk(0, 0);
    copy_chunk(1, 1);

    for (int c = 0; c < 5; c++) {
        if (c < 4) { CP_WAIT1(); } else { CP_WAIT0(); }
        __syncthreads();
        const float* Ps = sm + (c & 1) * PV_STAGE;
        const float* Vs = Ps + 80 * PS;
        #pragma unroll 4
        for (int k = 0; k < 32; k++) {
            unsigned long long bp[8];
            #pragma unroll
            for (int u = 0; u < 8; u++)
                bp[u] = lds64(&Vs[k * VS + 2 * tn + 32 * u]);
            #pragma unroll
            for (int v = 0; v < 5; v++) {
                unsigned long long a = dup2(Ps[(tm * 5 + v) * PS + k]);
                #pragma unroll
                for (int u = 0; u < 8; u++) ffma2(acc[v][u], a, bp[u]);
            }
        }
        __syncthreads();
        if (c < 3) copy_chunk(c + 2, c & 1);
    }

    #pragma unroll
    for (int v = 0; v < 5; v++) {
        size_t base = (size_t)(i0 + tm * 5 + v) * DD + d0 + 2 * tn;
        #pragma unroll
        for (int u = 0; u < 8; u++)
            *(float2*)&O[base + 32 * u] = unpk(acc[v][u]);
    }
}

// ---------------- host launcher --------------------------------------------
extern "C" void kernel_launch(void* const* d_in, const int* in_sizes, int n_in,
                              void* d_out, int out_size)
{
    const float* x      = (const float*)d_in[0];
    const float* w_qkv  = (const float*)d_in[1];
    const float* w_dw   = (const float*)d_in[2];
    const float* w_t    = (const float*)d_in[3];
    const float* b_t    = (const float*)d_in[4];
    const float* temp   = (const float*)d_in[5];
    const float* w_out  = (const float*)d_in[6];
    float* out = (float*)d_out;

    float *qkv0, *obuf;
    cudaGetSymbolAddress((void**)&qkv0, g_qkv0);
    cudaGetSymbolAddress((void**)&obuf, g_O);

    const int qk_smem = 2 * QK_STG * 4;     // 126976 B
    const int pv_smem = 2 * PV_STAGE * 4;   // 90624 B
    cudaFuncSetAttribute(qk_gemm7, cudaFuncAttributeMaxDynamicSharedMemorySize, qk_smem);
    cudaFuncSetAttribute(pv_gemm5, cudaFuncAttributeMaxDynamicSharedMemorySize, pv_smem);

    // K1: qkv projection (192 x 40960 per batch)
    gemm_proj2<<<dim3(THW / 128, C3 / 64, BB), 128>>>(
        w_qkv, x, qkv0, (long)CC * THW, (long)C3 * THW);

    // K2: depthwise 3x3 + temporal mix (16x64 strips)
    dwconv_tmix3<<<dim3(4, BB * C3), 256>>>(w_dw, w_t, b_t);

    // K3a: q/k row norms
    norms_kernel<<<640, 256>>>();

    // K3b: split-K scores (interleaved B, conflict-free LDS)
    qk_gemm7<<<dim3(BH, KSPL), 512, qk_smem>>>();

    // K3c: reduce + scale + softmax
    softmax2<<<(BH * NN) / 8, 256>>>(temp);

    // K3d: O = P V (2 CTAs/SM, cp.async)
    pv_gemm5<<<dim3(DD / 256, NN / 80, BH), 256, pv_smem>>>();

    // K7: final projection -> d_out
    gemm_proj2<<<dim3(THW / 128, 1, BB), 128>>>(
        w_out, obuf, out, (long)CC * THW, (long)CC * THW);
}

// round 12
// speedup vs baseline: 1.2342x; 1.0247x over previous
#include <cuda_runtime.h>
#include <math.h>
#include <stdint.h>

#define BB 4
#define CC 64
#define C3 192
#define TT 10
#define HH 64
#define WW 64
#define HW 4096
#define THW 40960
#define HEADS 4
#define CPH 16
#define NN 160
#define DD 4096
#define BH (BB*HEADS)
#define KSPL 8
#define KCH (DD/KSPL)   // 512

// ---------------- scratch (device globals) ---------------------------------
__device__ float g_qkv0[(size_t)BB * C3 * THW];
__device__ float g_qkv1[(size_t)BB * C3 * THW];
__device__ float g_Spart[(size_t)KSPL * BH * NN * NN];
__device__ float g_S[(size_t)BH * NN * NN];
__device__ float g_invq[BH * NN];
__device__ float g_invk[BH * NN];
__device__ float g_O[(size_t)BB * CC * THW];

// ---------------- packed f32x2 helpers --------------------------------------
__device__ __forceinline__ void ffma2(unsigned long long& d,
                                      unsigned long long a, unsigned long long b) {
    asm("fma.rn.f32x2 %0, %1, %2, %0;" : "+l"(d) : "l"(a), "l"(b));
}
__device__ __forceinline__ unsigned long long dup2(float x) {
    unsigned long long r;
    asm("mov.b64 %0, {%1, %1};" : "=l"(r) : "f"(x));
    return r;
}
__device__ __forceinline__ float2 unpk(unsigned long long v) {
    float2 r;
    asm("mov.b64 {%0, %1}, %2;" : "=f"(r.x), "=f"(r.y) : "l"(v));
    return r;
}
__device__ __forceinline__ unsigned long long lds64(const float* p) {
    return *(const unsigned long long*)p;
}
__device__ __forceinline__ uint32_t smem_u32(const void* p) {
    uint32_t a;
    asm("{ .reg .u64 t; cvta.to.shared.u64 t, %1; cvt.u32.u64 %0, t; }" : "=r"(a) : "l"(p));
    return a;
}
__device__ __forceinline__ void cpasync16(uint32_t dst, const void* src) {
    asm volatile("cp.async.cg.shared.global [%0], [%1], 16;" :: "r"(dst), "l"(src));
}
#define CP_COMMIT() asm volatile("cp.async.commit_group;" ::: "memory")
#define CP_WAIT1()  asm volatile("cp.async.wait_group 1;" ::: "memory")
#define CP_WAIT0()  asm volatile("cp.async.wait_group 0;" ::: "memory")

// ---------------- K1 / K7: projection GEMM (FFMA2, multi-CTA/SM) ------------
__global__ __launch_bounds__(128) void gemm_proj2(
    const float* __restrict__ W, const float* __restrict__ X, float* __restrict__ Y,
    long xbstride, long ybstride)
{
    __shared__ __align__(16) float As2[32][132];
    __shared__ __align__(16) float Bs[32][132];
    const int b  = blockIdx.z;
    const int m0 = blockIdx.y * 64;
    const int p0 = blockIdx.x * 128;
    const float* Xb = X + (size_t)b * xbstride;
    float*       Yb = Y + (size_t)b * ybstride;
    const int tid = threadIdx.x;
    const int tm = tid >> 4, tn = tid & 15;

    unsigned long long acc[8][4];
    #pragma unroll
    for (int i = 0; i < 8; i++)
        #pragma unroll
        for (int j = 0; j < 4; j++) acc[i][j] = 0ull;

    for (int kb = 0; kb < 64; kb += 32) {
        #pragma unroll
        for (int j = 0; j < 4; j++) {
            int idx = tid + j * 128;
            int row = idx >> 3;
            int kc  = (idx & 7) * 4;
            float4 w4 = *(const float4*)&W[(size_t)(m0 + row) * 64 + kb + kc];
            *(unsigned long long*)&As2[kc + 0][2 * row] = dup2(w4.x);
            *(unsigned long long*)&As2[kc + 1][2 * row] = dup2(w4.y);
            *(unsigned long long*)&As2[kc + 2][2 * row] = dup2(w4.z);
            *(unsigned long long*)&As2[kc + 3][2 * row] = dup2(w4.w);
        }
        #pragma unroll
        for (int j = 0; j < 8; j++) {
            int idx = tid + j * 128;
            int row = idx >> 5;
            int col = (idx & 31) * 4;
            *(float4*)&Bs[row][col] = *(const float4*)&Xb[(size_t)(kb + row) * THW + p0 + col];
        }
        __syncthreads();
        #pragma unroll 4
        for (int k = 0; k < 32; k++) {
            unsigned long long a[8], bp[4];
            #pragma unroll
            for (int mi = 0; mi < 8; mi++) a[mi] = lds64(&As2[k][2 * (tm * 8 + mi)]);
            #pragma unroll
            for (int u = 0; u < 4; u++)    bp[u] = lds64(&Bs[k][2 * tn + 32 * u]);
            #pragma unroll
            for (int mi = 0; mi < 8; mi++)
                #pragma unroll
                for (int u = 0; u < 4; u++) ffma2(acc[mi][u], a[mi], bp[u]);
        }
        __syncthreads();
    }
    #pragma unroll
    for (int mi = 0; mi < 8; mi++) {
        size_t base = (size_t)(m0 + tm * 8 + mi) * THW + p0 + 2 * tn;
        #pragma unroll
        for (int u = 0; u < 4; u++)
            *(float2*)&Yb[base + 32 * u] = unpk(acc[mi][u]);
    }
}

// ---------------- K2: depthwise 3x3 + temporal mix, 16x64 strips -------------
// channel range [c0, c0+cn); grid (4 strips, BB*cn)
__global__ __launch_bounds__(256) void dwconv_tmix3(
    const float* __restrict__ wdw, const float* __restrict__ wt,
    const float* __restrict__ bt, int c0, int cn)
{
    __shared__ __align__(16) float tile[TT][18][68];
    __shared__ float wts[TT * TT + TT];
    const int by = blockIdx.y;
    const int b  = by / cn;
    const int c  = c0 + by % cn;
    const int bc = b * C3 + c;
    const int h0 = blockIdx.x * 16;
    const float* src = g_qkv0 + (size_t)bc * THW;
    float*       dst = g_qkv1 + (size_t)bc * THW;
    const int tid = threadIdx.x;

    if (tid < TT * TT + TT)
        wts[tid] = (tid < TT * TT) ? wt[tid] : bt[tid - TT * TT];

    for (int idx = tid; idx < TT * 18 * 66; idx += 256) {
        int t = idx / (18 * 66);
        int rem = idx % (18 * 66);
        int y = rem / 66, x = rem % 66;
        int gh = h0 + y - 1, gw = x - 1;
        float v = 0.f;
        if (gh >= 0 && gh < HH && gw >= 0 && gw < WW)
            v = src[(size_t)t * HW + gh * WW + gw];
        tile[t][y][x] = v;
    }
    __syncthreads();

    float wd[9];
    #pragma unroll
    for (int i = 0; i < 9; i++) wd[i] = wdw[c * 9 + i];

    const int y  = tid >> 4;
    const int x0 = (tid & 15) * 4;

    float cv[4][TT];
    #pragma unroll
    for (int xx = 0; xx < 4; xx++)
        #pragma unroll
        for (int t = 0; t < TT; t++) cv[xx][t] = 0.f;

    #pragma unroll
    for (int t = 0; t < TT; t++) {
        #pragma unroll
        for (int kh = 0; kh < 3; kh++) {
            const float* row = &tile[t][y + kh][x0];
            float4 q = *(const float4*)row;
            float2 r2 = *(const float2*)(row + 4);
            float w0 = wd[kh * 3], w1 = wd[kh * 3 + 1], w2 = wd[kh * 3 + 2];
            cv[0][t] += w0 * q.x + w1 * q.y  + w2 * q.z;
            cv[1][t] += w0 * q.y + w1 * q.z  + w2 * q.w;
            cv[2][t] += w0 * q.z + w1 * q.w  + w2 * r2.x;
            cv[3][t] += w0 * q.w + w1 * r2.x + w2 * r2.y;
        }
    }

    const int hw = (h0 + y) * WW + x0;
    #pragma unroll
    for (int s = 0; s < TT; s++) {
        float bs = wts[TT * TT + s];
        float4 o = make_float4(bs, bs, bs, bs);
        #pragma unroll
        for (int t = 0; t < TT; t++) {
            float w = wts[s * TT + t];
            o.x += w * cv[0][t];
            o.y += w * cv[1][t];
            o.z += w * cv[2][t];
            o.w += w * cv[3][t];
        }
        *(float4*)&dst[(size_t)s * HW + hw] = o;
    }
}

// ---------------- K3a: L2 norms of q/k rows ---------------------------------
__global__ __launch_bounds__(256) void norms_kernel()
{
    const int warp = (blockIdx.x * 256 + threadIdx.x) >> 5;
    const int lane = threadIdx.x & 31;
    if (warp >= 2 * BH * NN) return;
    const int qk = warp / (BH * NN);
    const int r  = warp % (BH * NN);
    const int bh = r / NN, i = r % NN;
    const int b = bh / HEADS, h = bh % HEADS;
    const float* row = g_qkv1 + ((size_t)b * C3 + qk * CC + h * CPH) * THW + (size_t)i * DD;
    float s = 0.f;
    for (int d = lane * 4; d < DD; d += 128) {
        float4 v = *(const float4*)&row[d];
        s += v.x * v.x + v.y * v.y + v.z * v.z + v.w * v.w;
    }
    #pragma unroll
    for (int off = 16; off; off >>= 1) s += __shfl_xor_sync(0xffffffffu, s, off);
    if (lane == 0) {
        float inv = 1.f / fmaxf(sqrtf(s), 1e-12f);
        (qk ? g_invk : g_invq)[bh * NN + i] = inv;
    }
}

// ---------------- K3b: S partials = Q K^T -----------------------------------
#define QAS 330                        // dup-A row stride (floats)
#define QBS 166                        // K row stride (floats)
#define QK_STG (32 * QAS + 32 * QBS)   // one stage, floats

__global__ __launch_bounds__(512, 1) void qk_gemm7()
{
    extern __shared__ __align__(16) float sm[];
    const int bh = blockIdx.x;
    const int ks = blockIdx.y;
    const int b = bh >> 2, h = bh & 3;
    const float* Q  = g_qkv1 + ((size_t)b * C3 + h * CPH) * THW + (size_t)ks * KCH;
    const float* Kp = Q + (size_t)CC * THW;
    const int tid = threadIdx.x;
    const int tm = tid >> 4;
    const int tn = tid & 15;

    int lisK[5], lrow[5], lseg[5];
    #pragma unroll
    for (int j = 0; j < 5; j++) {
        int idx = tid + j * 512;
        lisK[j] = idx >= 1280;
        int l = idx - lisK[j] * 1280;
        lrow[j] = l >> 3;
        lseg[j] = (l & 7) * 4;
    }

    unsigned long long acc[5][5];
    #pragma unroll
    for (int i = 0; i < 5; i++)
        #pragma unroll
        for (int j = 0; j < 5; j++) acc[i][j] = 0ull;

    float4 r[5];
    auto gload = [&](int c) {
        const int kb = c * 32;
        #pragma unroll
        for (int j = 0; j < 5; j++)
            r[j] = *(const float4*)((lisK[j] ? Kp : Q) + (size_t)lrow[j] * DD + kb + lseg[j]);
    };
    auto sstore = [&](int s) {
        float* Qs2 = sm + s * QK_STG;
        float* Ksh = Qs2 + 32 * QAS;
        #pragma unroll
        for (int j = 0; j < 5; j++) {
            if (lisK[j]) {
                Ksh[(lseg[j] + 0) * QBS + lrow[j]] = r[j].x;
                Ksh[(lseg[j] + 1) * QBS + lrow[j]] = r[j].y;
                Ksh[(lseg[j] + 2) * QBS + lrow[j]] = r[j].z;
                Ksh[(lseg[j] + 3) * QBS + lrow[j]] = r[j].w;
            } else {
                *(unsigned long long*)&Qs2[(lseg[j] + 0) * QAS + 2 * lrow[j]] = dup2(r[j].x);
                *(unsigned long long*)&Qs2[(lseg[j] + 1) * QAS + 2 * lrow[j]] = dup2(r[j].y);
                *(unsigned long long*)&Qs2[(lseg[j] + 2) * QAS + 2 * lrow[j]] = dup2(r[j].z);
                *(unsigned long long*)&Qs2[(lseg[j] + 3) * QAS + 2 * lrow[j]] = dup2(r[j].w);
            }
        }
    };

    gload(0);
    sstore(0);
    __syncthreads();

    for (int c = 0; c < 16; c++) {
        if (c < 15) gload(c + 1);
        const float* Qs2 = sm + (c & 1) * QK_STG;
        const float* Ksh = Qs2 + 32 * QAS;
        #pragma unroll 4
        for (int k = 0; k < 32; k++) {
            unsigned long long a[5], bp[5];
            #pragma unroll
            for (int g = 0; g < 5; g++) a[g]  = lds64(&Qs2[k * QAS + 10 * tm + 2 * g]);
            #pragma unroll
            for (int u = 0; u < 5; u++) bp[u] = lds64(&Ksh[k * QBS + 2 * tn + 32 * u]);
            #pragma unroll
            for (int g = 0; g < 5; g++)
                #pragma unroll
                for (int u = 0; u < 5; u++) ffma2(acc[g][u], a[g], bp[u]);
        }
        if (c < 15) sstore((c + 1) & 1);
        __syncthreads();
    }

    float* Sp = g_Spart + ((size_t)ks * BH + bh) * NN * NN;
    #pragma unroll
    for (int g = 0; g < 5; g++) {
        int gi = tm * 5 + g;
        #pragma unroll
        for (int u = 0; u < 5; u++)
            *(float2*)&Sp[(size_t)gi * NN + 2 * tn + 32 * u] = unpk(acc[g][u]);
    }
}

// ---------------- K3c: reduce split-K + scale + softmax ---------------------
__global__ __launch_bounds__(256) void softmax2(const float* __restrict__ temp)
{
    const int warp = (blockIdx.x * 256 + threadIdx.x) >> 5;
    const int lane = threadIdx.x & 31;
    if (warp >= BH * NN) return;
    const int bh = warp / NN, i = warp % NN;
    const int h = bh & 3;
    const float scale_i = g_invq[bh * NN + i] * temp[h];
    float vals[5];
    float mx = -1e30f;
    #pragma unroll
    for (int j5 = 0; j5 < 5; j5++) {
        int j = lane + j5 * 32;
        float s = 0.f;
        #pragma unroll
        for (int ks = 0; ks < KSPL; ks++)
            s += g_Spart[(((size_t)ks * BH + bh) * NN + i) * NN + j];
        vals[j5] = s * scale_i * g_invk[bh * NN + j];
        mx = fmaxf(mx, vals[j5]);
    }
    #pragma unroll
    for (int off = 16; off; off >>= 1) mx = fmaxf(mx, __shfl_xor_sync(0xffffffffu, mx, off));
    float s = 0.f;
    #pragma unroll
    for (int j5 = 0; j5 < 5; j5++) { vals[j5] = __expf(vals[j5] - mx); s += vals[j5]; }
    #pragma unroll
    for (int off = 16; off; off >>= 1) s += __shfl_xor_sync(0xffffffffu, s, off);
    const float invs = 1.f / s;
    float* row = g_S + (size_t)bh * NN * NN + (size_t)i * NN;
    #pragma unroll
    for (int j5 = 0; j5 < 5; j5++) row[lane + j5 * 32] = vals[j5] * invs;
}

// ---------------- K3d: O = P V ----------------------------------------------
#define PS 36                          // P row stride (floats)
#define VS 264                         // V row stride (floats)
#define PV_STAGE (80 * PS + 32 * VS)   // floats

__global__ __launch_bounds__(256, 2) void pv_gemm5()
{
    extern __shared__ __align__(16) float sm[];
    const uint32_t sbase = smem_u32(sm);
    const int bh = blockIdx.z;
    const int b = bh >> 2, h = bh & 3;
    const int i0 = blockIdx.y * 80;
    const int d0 = blockIdx.x * 256;
    const float* P = g_S + (size_t)bh * NN * NN;
    const float* V = g_qkv1 + ((size_t)b * C3 + 2 * CC + h * CPH) * THW;
    float*       O = g_O   + ((size_t)b * CC + h * CPH) * THW;
    const int tid = threadIdx.x;
    const int tm = tid >> 4, tn = tid & 15;

    auto copy_chunk = [&](int c, int s) {
        const int kb = c * 32;
        #pragma unroll
        for (int j = 0; j < 3; j++) {
            int idx = tid + j * 256;
            if (idx < 640) {
                int row = idx >> 3, seg = idx & 7;
                cpasync16(sbase + (uint32_t)(s * PV_STAGE + row * PS + seg * 4) * 4u,
                          P + (size_t)(i0 + row) * NN + kb + seg * 4);
            }
        }
        #pragma unroll
        for (int j = 0; j < 8; j++) {
            int idx = tid + j * 256;
            int row = idx >> 6, col = (idx & 63) * 4;
            cpasync16(sbase + (uint32_t)(s * PV_STAGE + 80 * PS + row * VS + col) * 4u,
                      V + (size_t)(kb + row) * DD + d0 + col);
        }
        CP_COMMIT();
    };

    unsigned long long acc[5][8];
    #pragma unroll
    for (int i = 0; i < 5; i++)
        #pragma unroll
        for (int j = 0; j < 8; j++) acc[i][j] = 0ull;

    copy_chunk(0, 0);
    copy_chunk(1, 1);

    for (int c = 0; c < 5; c++) {
        if (c < 4) { CP_WAIT1(); } else { CP_WAIT0(); }
        __syncthreads();
        const float* Ps = sm + (c & 1) * PV_STAGE;
        const float* Vs = Ps + 80 * PS;
        #pragma unroll 4
        for (int k = 0; k < 32; k++) {
            unsigned long long bp[8];
            #pragma unroll
            for (int u = 0; u < 8; u++)
                bp[u] = lds64(&Vs[k * VS + 2 * tn + 32 * u]);
            #pragma unroll
            for (int v = 0; v < 5; v++) {
                unsigned long long a = dup2(Ps[(tm * 5 + v) * PS + k]);
                #pragma unroll
                for (int u = 0; u < 8; u++) ffma2(acc[v][u], a, bp[u]);
            }
        }
        __syncthreads();
        if (c < 3) copy_chunk(c + 2, c & 1);
    }

    #pragma unroll
    for (int v = 0; v < 5; v++) {
        size_t base = (size_t)(i0 + tm * 5 + v) * DD + d0 + 2 * tn;
        #pragma unroll
        for (int u = 0; u < 8; u++)
            *(float2*)&O[base + 32 * u] = unpk(acc[v][u]);
    }
}

// ---------------- host launcher --------------------------------------------
extern "C" void kernel_launch(void* const* d_in, const int* in_sizes, int n_in,
                              void* d_out, int out_size)
{
    const float* x      = (const float*)d_in[0];
    const float* w_qkv  = (const float*)d_in[1];
    const float* w_dw   = (const float*)d_in[2];
    const float* w_t    = (const float*)d_in[3];
    const float* b_t    = (const float*)d_in[4];
    const float* temp   = (const float*)d_in[5];
    const float* w_out  = (const float*)d_in[6];
    float* out = (float*)d_out;

    float *qkv0, *obuf;
    cudaGetSymbolAddress((void**)&qkv0, g_qkv0);
    cudaGetSymbolAddress((void**)&obuf, g_O);

    const int qk_smem = 2 * QK_STG * 4;     // 126976 B
    const int pv_smem = 2 * PV_STAGE * 4;   // 90624 B
    cudaFuncSetAttribute(qk_gemm7, cudaFuncAttributeMaxDynamicSharedMemorySize, qk_smem);
    cudaFuncSetAttribute(pv_gemm5, cudaFuncAttributeMaxDynamicSharedMemorySize, pv_smem);

    // fork/join resources (kernel_launch runs only a few times; handles are
    // created per call and never destroyed — no device-memory allocation)
    cudaStream_t s2;
    cudaEvent_t e1, e2;
    cudaStreamCreateWithFlags(&s2, cudaStreamNonBlocking);
    cudaEventCreateWithFlags(&e1, cudaEventDisableTiming);
    cudaEventCreateWithFlags(&e2, cudaEventDisableTiming);

    // K1: qkv projection (192 x 40960 per batch)
    gemm_proj2<<<dim3(THW / 128, C3 / 64, BB), 128>>>(
        w_qkv, x, qkv0, (long)CC * THW, (long)C3 * THW);

    // K2a: depthwise + temporal mix for q,k channels (critical path)
    dwconv_tmix3<<<dim3(4, BB * 128), 256>>>(w_dw, w_t, b_t, 0, 128);
    cudaEventRecord(e1, 0);

    // side stream: v channels + norms, overlapped with qk
    cudaStreamWaitEvent(s2, e1, 0);
    dwconv_tmix3<<<dim3(4, BB * 64), 256, 0, s2>>>(w_dw, w_t, b_t, 128, 64);
    norms_kernel<<<640, 256, 0, s2>>>();
    cudaEventRecord(e2, s2);

    // K3b: split-K scores (needs only q,k)
    qk_gemm7<<<dim3(BH, KSPL), 512, qk_smem>>>();

    // join: softmax needs norms; pv needs v
    cudaStreamWaitEvent(0, e2, 0);

    // K3c: reduce + scale + softmax
    softmax2<<<(BH * NN) / 8, 256>>>(temp);

    // K3d: O = P V
    pv_gemm5<<<dim3(DD / 256, NN / 80, BH), 256, pv_smem>>>();

    // K7: final projection -> d_out
    gemm_proj2<<<dim3(THW / 128, 1, BB), 128>>>(
        w_out, obuf, out, (long)CC * THW, (long)CC * THW);
}